// round 1
// baseline (speedup 1.0000x reference)
#include <cuda_runtime.h>
#include <math.h>

// Problem constants
#define NB    16      // N * S*S blocks
#define LSEQ  2048    // tokens per block (32*32*2)
#define CKD   32
#define CVD   64
#define NPOS  32768   // N*H*W2
#define EPSB  1e-5f

// ---------------- scratch (device globals; no allocation allowed) ----------
__device__ float g_q[NB * LSEQ * CKD];   // [nb][l][ck]  raw conv out
__device__ float g_k[NB * LSEQ * CKD];
__device__ float g_v[NB * LSEQ * CVD];   // [nb][l][cv]
__device__ float g_sum[64];
__device__ float g_sq[64];
__device__ float g_affa[64];   // 0..31 q, 32..63 k : y = raw*a + c
__device__ float g_affc[64];

// ---------------- kernel 0: zero the stat accumulators ---------------------
__global__ void zero_stats_kernel() {
    g_sum[threadIdx.x] = 0.0f;
    g_sq[threadIdx.x]  = 0.0f;
}

// ---------------- kernel 1: conv1x1 + blocked scatter + stats --------------
// grid 1024, block 128. Each block: 32 consecutive pixels of one image,
// each thread owns one output channel oc (0..31 q, 32..63 k, 64..127 v).
__global__ __launch_bounds__(128) void conv_kernel(
    const float* __restrict__ x,
    const float* __restrict__ Wq, const float* __restrict__ bq,
    const float* __restrict__ Wk, const float* __restrict__ bk,
    const float* __restrict__ Wv, const float* __restrict__ bv)
{
    __shared__ float xs[64 * 32];          // [c][pos], pos contiguous (float4-able)
    __shared__ float wsm[128 * 65];        // padded weight rows: wsm[oc*65+c]

    const int tid = threadIdx.x;
    const int p0  = blockIdx.x * 32;       // global pixel base (never crosses image)
    const int n      = p0 >> 13;           // /8192
    const int imgoff = p0 & 8191;

    // stage x tile: 64 channels x 32 pixels
    const float* xbase = x + (size_t)n * 64 * 8192 + imgoff;
    for (int f = tid; f < 64 * 32; f += 128) {
        int c = f >> 5, pos = f & 31;
        xs[c * 32 + pos] = xbase[c * 8192 + pos];
    }
    // stage weights (128 rows x 64, pad 65 to kill bank conflicts)
    for (int f = tid; f < 128 * 64; f += 128) {
        int o = f >> 6, c = f & 63;
        float w;
        if      (o < 32) w = Wq[o * 64 + c];
        else if (o < 64) w = Wk[(o - 32) * 64 + c];
        else             w = Wv[(o - 64) * 64 + c];
        wsm[o * 65 + c] = w;
    }
    __syncthreads();

    const int oc = tid;
    float bias;
    if      (oc < 32) bias = bq[oc];
    else if (oc < 64) bias = bk[oc - 32];
    else              bias = bv[oc - 64];

    float acc[32];
#pragma unroll
    for (int p = 0; p < 32; p++) acc[p] = bias;

    const float4* xs4 = (const float4*)xs;
#pragma unroll 8
    for (int c = 0; c < 64; c++) {
        float wv = wsm[oc * 65 + c];
#pragma unroll
        for (int p4 = 0; p4 < 8; p4++) {
            float4 xv = xs4[c * 8 + p4];
            acc[p4 * 4 + 0] += wv * xv.x;
            acc[p4 * 4 + 1] += wv * xv.y;
            acc[p4 * 4 + 2] += wv * xv.z;
            acc[p4 * 4 + 3] += wv * xv.w;
        }
    }

    // scatter into blocked layout + accumulate channel stats
    float s = 0.0f, sq = 0.0f;
#pragma unroll
    for (int pp = 0; pp < 32; pp++) {
        int q    = imgoff + pp;          // h*128 + w2
        int h    = q >> 7;
        int w2   = q & 127;
        int side = w2 >> 6;
        int w    = w2 & 63;
        int b    = ((h >> 5) << 1) | (w >> 5);
        int l    = ((((h & 31) << 5) | (w & 31)) << 1) | side;
        int nb   = (n << 2) | b;
        float v  = acc[pp];
        if      (oc < 32) g_q[(size_t)(nb * LSEQ + l) * CKD + oc]        = v;
        else if (oc < 64) g_k[(size_t)(nb * LSEQ + l) * CKD + (oc - 32)] = v;
        else              g_v[(size_t)(nb * LSEQ + l) * CVD + (oc - 64)] = v;
        s  += v;
        sq += v * v;
    }
    if (oc < 64) {
        atomicAdd(&g_sum[oc], s);
        atomicAdd(&g_sq[oc],  sq);
    }
}

// ---------------- kernel 2: fold BN into per-channel affine ----------------
__global__ void bn_kernel(const float* __restrict__ gq, const float* __restrict__ betaq,
                          const float* __restrict__ gk, const float* __restrict__ betak)
{
    int c = threadIdx.x;  // 0..63
    float mean = g_sum[c] / (float)NPOS;
    float var  = g_sq[c] / (float)NPOS - mean * mean;
    float gg   = (c < 32) ? gq[c]    : gk[c - 32];
    float be   = (c < 32) ? betaq[c] : betak[c - 32];
    float a    = gg * rsqrtf(var + EPSB);
    g_affa[c] = a;
    g_affc[c] = be - mean * a;
}

// ---------------- kernel 3: flash attention --------------------------------
// grid (16 q-chunks, 16 nb), 256 threads (16x16), 1 CTA/SM (132KB smem).
// Per CTA: 128 q rows; loop 16 key tiles of 128; online softmax; O in regs.
#define SQ_PITCH 132   // [32][132]   (multiple of 4, conflict-free fragments)
#define SP_PITCH 128   // [128][128]
#define OP_PITCH 68    // output staging pitch inside sP region
#define SMEM_FLOATS (2 * 32 * SQ_PITCH + 128 * 64 + 128 * 128)  // 33024

extern __shared__ float s_attn[];

__global__ __launch_bounds__(256, 1) void attn_kernel(float* __restrict__ out)
{
    float* sQ = s_attn;                    // [32][132]  (ck-major, scaled+affine)
    float* sK = sQ + 32 * SQ_PITCH;        // [32][132]
    float* sV = sK + 32 * SQ_PITCH;        // [128][64]
    float* sP = sV + 128 * 64;             // [128][128], reused as O staging

    const int tid = threadIdx.x;
    const int tx  = tid & 15;
    const int ty  = tid >> 4;
    const int nb    = blockIdx.y;
    const int chunk = blockIdx.x;
    const int qbase = chunk * 128;

    // ---- load Q tile (apply q-affine and 1/sqrt(CK)) ----
    const float* qg = g_q + (size_t)nb * LSEQ * CKD + (size_t)qbase * CKD;
    for (int f = tid; f < 128 * 32; f += 256) {
        int ck = f & 31, lr = f >> 5;
        float raw = qg[lr * CKD + ck];
        sQ[ck * SQ_PITCH + lr] =
            (raw * g_affa[ck] + g_affc[ck]) * 0.17677669529663687f;  // 1/sqrt(32)
    }

    float m_r[8], l_r[8], O[8][4];
#pragma unroll
    for (int u = 0; u < 8; u++) {
        m_r[u] = -1e30f; l_r[u] = 0.0f;
#pragma unroll
        for (int c = 0; c < 4; c++) O[u][c] = 0.0f;
    }

    for (int kt = 0; kt < 16; kt++) {
        __syncthreads();   // prior PV done with sK/sV (and kt=0: sQ visible)

        // ---- load K tile (k-affine) + V tile ----
        const float* kg = g_k + (size_t)nb * LSEQ * CKD + (size_t)(kt * 128) * CKD;
        for (int f = tid; f < 128 * 32; f += 256) {
            int ck = f & 31, lr = f >> 5;
            float raw = kg[lr * CKD + ck];
            sK[ck * SQ_PITCH + lr] = raw * g_affa[32 + ck] + g_affc[32 + ck];
        }
        const float* vg = g_v + (size_t)nb * LSEQ * CVD + (size_t)(kt * 128) * CVD;
        for (int f = tid; f < 128 * 64; f += 256) sV[f] = vg[f];
        __syncthreads();

        // ---- S = Q K^T  (8x8 per thread, k=32) ----
        float S[8][8];
#pragma unroll
        for (int u = 0; u < 8; u++)
#pragma unroll
            for (int v = 0; v < 8; v++) S[u][v] = 0.0f;

#pragma unroll 2
        for (int kk = 0; kk < 32; kk++) {
            const float* qr = &sQ[kk * SQ_PITCH + ty * 8];
            const float* kr = &sK[kk * SQ_PITCH + tx * 8];
            float4 qa = *(const float4*)qr;
            float4 qb = *(const float4*)(qr + 4);
            float4 ka = *(const float4*)kr;
            float4 kb = *(const float4*)(kr + 4);
            float qv[8] = {qa.x, qa.y, qa.z, qa.w, qb.x, qb.y, qb.z, qb.w};
            float kv[8] = {ka.x, ka.y, ka.z, ka.w, kb.x, kb.y, kb.z, kb.w};
#pragma unroll
            for (int u = 0; u < 8; u++)
#pragma unroll
                for (int v = 0; v < 8; v++) S[u][v] += qv[u] * kv[v];
        }

        // ---- online softmax (row groups = 16 lanes sharing ty) ----
#pragma unroll
        for (int u = 0; u < 8; u++) {
            float tm = S[u][0];
#pragma unroll
            for (int v = 1; v < 8; v++) tm = fmaxf(tm, S[u][v]);
#pragma unroll
            for (int off = 8; off > 0; off >>= 1)
                tm = fmaxf(tm, __shfl_xor_sync(0xffffffffu, tm, off, 16));

            float nm    = fmaxf(m_r[u], tm);
            float alpha = __expf(m_r[u] - nm);
            m_r[u] = nm;

            float rs = 0.0f;
#pragma unroll
            for (int v = 0; v < 8; v++) {
                float p = __expf(S[u][v] - nm);
                S[u][v] = p;
                rs += p;
            }
#pragma unroll
            for (int off = 8; off > 0; off >>= 1)
                rs += __shfl_xor_sync(0xffffffffu, rs, off, 16);

            l_r[u] = l_r[u] * alpha + rs;
#pragma unroll
            for (int c = 0; c < 4; c++) O[u][c] *= alpha;

            float* pr = &sP[(ty * 8 + u) * SP_PITCH + tx * 8];
            *(float4*)pr       = make_float4(S[u][0], S[u][1], S[u][2], S[u][3]);
            *(float4*)(pr + 4) = make_float4(S[u][4], S[u][5], S[u][6], S[u][7]);
        }
        __syncthreads();

        // ---- O += P V  (k = 128, step 4) ----
        for (int k0 = 0; k0 < 128; k0 += 4) {
            float4 va0 = *(const float4*)&sV[(k0 + 0) * 64 + tx * 4];
            float4 va1 = *(const float4*)&sV[(k0 + 1) * 64 + tx * 4];
            float4 va2 = *(const float4*)&sV[(k0 + 2) * 64 + tx * 4];
            float4 va3 = *(const float4*)&sV[(k0 + 3) * 64 + tx * 4];
#pragma unroll
            for (int u = 0; u < 8; u++) {
                float4 pv = *(const float4*)&sP[(ty * 8 + u) * SP_PITCH + k0];
                O[u][0] += pv.x * va0.x + pv.y * va1.x + pv.z * va2.x + pv.w * va3.x;
                O[u][1] += pv.x * va0.y + pv.y * va1.y + pv.z * va2.y + pv.w * va3.y;
                O[u][2] += pv.x * va0.z + pv.y * va1.z + pv.z * va2.z + pv.w * va3.z;
                O[u][3] += pv.x * va0.w + pv.y * va1.w + pv.z * va2.w + pv.w * va3.w;
            }
        }
    }

    // ---- finalize: divide by row sum, stage, coalesced scatter to out ----
    __syncthreads();
#pragma unroll
    for (int u = 0; u < 8; u++) {
        float inv = 1.0f / l_r[u];
        float* op = &sP[(ty * 8 + u) * OP_PITCH + tx * 4];
        *(float4*)op = make_float4(O[u][0] * inv, O[u][1] * inv,
                                   O[u][2] * inv, O[u][3] * inv);
    }
    __syncthreads();

    const int n = nb >> 2, b = nb & 3;
    const int bi = b >> 1, bj = b & 1;
    for (int e = tid; e < 8192; e += 256) {
        int wl   = e & 31;
        int side = (e >> 5) & 1;
        int hlo  = (e >> 6) & 1;
        int cv   = e >> 7;
        int ll   = hlo * 64 + wl * 2 + side;           // local row in chunk
        int h    = bi * 32 + chunk * 2 + hlo;
        int w2   = side * 64 + bj * 32 + wl;
        out[(((size_t)(n * 64 + cv)) * 64 + h) * 128 + w2] = sP[ll * OP_PITCH + cv];
    }
}

// ---------------- launch ---------------------------------------------------
extern "C" void kernel_launch(void* const* d_in, const int* in_sizes, int n_in,
                              void* d_out, int out_size)
{
    (void)in_sizes; (void)n_in; (void)out_size;
    const float* x     = (const float*)d_in[0];
    const float* Wq    = (const float*)d_in[1];
    const float* bq    = (const float*)d_in[2];
    const float* gq    = (const float*)d_in[3];
    const float* betaq = (const float*)d_in[4];
    const float* Wk    = (const float*)d_in[5];
    const float* bk    = (const float*)d_in[6];
    const float* gk    = (const float*)d_in[7];
    const float* betak = (const float*)d_in[8];
    const float* Wv    = (const float*)d_in[9];
    const float* bv    = (const float*)d_in[10];
    float* out = (float*)d_out;

    cudaFuncSetAttribute(attn_kernel, cudaFuncAttributeMaxDynamicSharedMemorySize,
                         SMEM_FLOATS * (int)sizeof(float));

    zero_stats_kernel<<<1, 64>>>();
    conv_kernel<<<1024, 128>>>(x, Wq, bq, Wk, bk, Wv, bv);
    bn_kernel<<<1, 64>>>(gq, betaq, gk, betak);
    attn_kernel<<<dim3(16, 16), 256, SMEM_FLOATS * sizeof(float)>>>(out);
}

// round 3
// speedup vs baseline: 2.1086x; 2.1086x over previous
#include <cuda_runtime.h>
#include <cuda_bf16.h>
#include <math.h>
#include <cstdint>

// ---------------------------------------------------------------- constants
#define NBLK  16
#define LSEQ  2048
#define CKD   32
#define CVD   64
#define NPOSF 32768.0f
#define EPSB  1e-5f
// (1/sqrt(32)) * log2(e) folded into q
#define SCALE_Q 0.25505654350925196f

// ---------------------------------------------------------------- scratch
__device__ float g_q [NBLK * LSEQ * CKD];
__device__ float g_k [NBLK * LSEQ * CKD];
__device__ float g_vt[NBLK * CVD * LSEQ];           // [nb][cv][l]
__device__ __nv_bfloat16 g_qhi[NBLK * LSEQ * CKD];
__device__ __nv_bfloat16 g_qlo[NBLK * LSEQ * CKD];
__device__ __nv_bfloat16 g_khi[NBLK * LSEQ * CKD];
__device__ __nv_bfloat16 g_klo[NBLK * LSEQ * CKD];
__device__ __nv_bfloat16 g_vthi[NBLK * CVD * LSEQ];
__device__ __nv_bfloat16 g_vtlo[NBLK * CVD * LSEQ];
__device__ float g_sum[64], g_sq[64], g_affa[64], g_affc[64];

// ---------------------------------------------------------------- helpers
__device__ __forceinline__ void mma_bf16(float* c, const uint32_t* a,
                                         uint32_t b0, uint32_t b1) {
    asm volatile(
        "mma.sync.aligned.m16n8k16.row.col.f32.bf16.bf16.f32 "
        "{%0,%1,%2,%3}, {%4,%5,%6,%7}, {%8,%9}, {%0,%1,%2,%3};"
        : "+f"(c[0]), "+f"(c[1]), "+f"(c[2]), "+f"(c[3])
        : "r"(a[0]), "r"(a[1]), "r"(a[2]), "r"(a[3]), "r"(b0), "r"(b1));
}
// pack (lo -> bits[0:16], hi -> bits[16:32])
__device__ __forceinline__ uint32_t pack_bf16x2(float lo, float hi) {
    uint32_t r;
    asm("cvt.rn.bf16x2.f32 %0, %1, %2;" : "=r"(r) : "f"(hi), "f"(lo));
    return r;
}
__device__ __forceinline__ void split2(float p0, float p1, uint32_t& hw, uint32_t& lw) {
    hw = pack_bf16x2(p0, p1);
    float h0 = __uint_as_float(hw << 16);
    float h1 = __uint_as_float(hw & 0xffff0000u);
    lw = pack_bf16x2(p0 - h0, p1 - h1);
}
__device__ __forceinline__ uint32_t ld32s(const __nv_bfloat16* p) {
    return *(const uint32_t*)p;
}

// ---------------------------------------------------------------- kernel 0
__global__ void zero_stats_kernel() { g_sum[threadIdx.x] = 0.f; g_sq[threadIdx.x] = 0.f; }

// ---------------------------------------------------------------- kernel 1: conv1x1
__global__ __launch_bounds__(128) void conv_kernel(
    const float* __restrict__ x,
    const float* __restrict__ Wq, const float* __restrict__ bq,
    const float* __restrict__ Wk, const float* __restrict__ bk,
    const float* __restrict__ Wv, const float* __restrict__ bv)
{
    __shared__ float xs[64 * 32];
    __shared__ float wsm[128 * 65];
    const int tid = threadIdx.x;
    const int p0  = blockIdx.x * 32;
    const int n      = p0 >> 13;
    const int imgoff = p0 & 8191;

    const float* xbase = x + (size_t)n * 64 * 8192 + imgoff;
    for (int f = tid; f < 64 * 32; f += 128) {
        int c = f >> 5, pos = f & 31;
        xs[c * 32 + pos] = xbase[c * 8192 + pos];
    }
    for (int f = tid; f < 128 * 64; f += 128) {
        int o = f >> 6, c = f & 63;
        float w;
        if      (o < 32) w = Wq[o * 64 + c];
        else if (o < 64) w = Wk[(o - 32) * 64 + c];
        else             w = Wv[(o - 64) * 64 + c];
        wsm[o * 65 + c] = w;
    }
    __syncthreads();

    const int oc = tid;
    float bias;
    if      (oc < 32) bias = bq[oc];
    else if (oc < 64) bias = bk[oc - 32];
    else              bias = bv[oc - 64];

    float acc[32];
#pragma unroll
    for (int p = 0; p < 32; p++) acc[p] = bias;

    const float4* xs4 = (const float4*)xs;
#pragma unroll 8
    for (int c = 0; c < 64; c++) {
        float wv = wsm[oc * 65 + c];
#pragma unroll
        for (int p4 = 0; p4 < 8; p4++) {
            float4 xv = xs4[c * 8 + p4];
            acc[p4 * 4 + 0] += wv * xv.x;
            acc[p4 * 4 + 1] += wv * xv.y;
            acc[p4 * 4 + 2] += wv * xv.z;
            acc[p4 * 4 + 3] += wv * xv.w;
        }
    }

    float s = 0.f, sq = 0.f;
#pragma unroll
    for (int pp = 0; pp < 32; pp++) {
        int q    = imgoff + pp;
        int h    = q >> 7;
        int w2   = q & 127;
        int side = w2 >> 6;
        int w    = w2 & 63;
        int b    = ((h >> 5) << 1) | (w >> 5);
        int l    = ((((h & 31) << 5) | (w & 31)) << 1) | side;
        int nb   = (n << 2) | b;
        float v  = acc[pp];
        if      (oc < 32) g_q[(size_t)(nb * LSEQ + l) * CKD + oc]         = v;
        else if (oc < 64) g_k[(size_t)(nb * LSEQ + l) * CKD + (oc - 32)]  = v;
        else              g_vt[((size_t)nb * CVD + (oc - 64)) * LSEQ + l] = v;
        s += v; sq += v * v;
    }
    if (oc < 64) { atomicAdd(&g_sum[oc], s); atomicAdd(&g_sq[oc], sq); }
}

// ---------------------------------------------------------------- kernel 2: BN fold
__global__ void bn_kernel(const float* __restrict__ gq, const float* __restrict__ betaq,
                          const float* __restrict__ gk, const float* __restrict__ betak)
{
    int c = threadIdx.x;
    float mean = g_sum[c] / NPOSF;
    float var  = g_sq[c] / NPOSF - mean * mean;
    float gg   = (c < 32) ? gq[c]    : gk[c - 32];
    float be   = (c < 32) ? betaq[c] : betak[c - 32];
    float a    = gg * rsqrtf(var + EPSB);
    g_affa[c] = a;
    g_affc[c] = be - mean * a;
}

// ---------------------------------------------------------------- prep kernels
__device__ __forceinline__ void split_bf(float y, __nv_bfloat16& h, __nv_bfloat16& l) {
    h = __float2bfloat16_rn(y);
    l = __float2bfloat16_rn(y - __bfloat162float(h));
}

__global__ __launch_bounds__(256) void prep_qk_kernel() {
    int idx = blockIdx.x * 256 + threadIdx.x;
    int which = idx >> 20;
    int i = idx & 1048575;
    int ck = i & 31;
    if (which == 0) {
        float y = (g_q[i] * g_affa[ck] + g_affc[ck]) * SCALE_Q;
        split_bf(y, g_qhi[i], g_qlo[i]);
    } else {
        float y = g_k[i] * g_affa[32 + ck] + g_affc[32 + ck];
        split_bf(y, g_khi[i], g_klo[i]);
    }
}

__global__ __launch_bounds__(256) void prep_v_kernel() {
    int idx = blockIdx.x * 256 + threadIdx.x;
    float y = g_vt[idx];
    split_bf(y, g_vthi[idx], g_vtlo[idx]);
}

// ---------------------------------------------------------------- attention
// smem (bytes):
#define KPITCH 40          // bf16 elems per K/Q row
#define VPITCH 136         // bf16 elems per V row
#define OFF_KH 0           // 128*80   = 10240
#define OFF_KL 10240       // 10240
#define OFF_VH 20480       // 64*272   = 17408
#define OFF_VL 37888       // 17408
#define OFF_QH 55296       // 10240
#define OFF_QL 65536       // 10240
#define OFF_RS 75776       // 2*128*4  = 1024
#define SMEM_BYTES 76800
#define STG_PITCH 66       // float staging pitch (overlays offset 0 at the end)

extern __shared__ char s_raw[];

__global__ __launch_bounds__(256) void attn_kernel(float* __restrict__ out)
{
    __nv_bfloat16* sKh = (__nv_bfloat16*)(s_raw + OFF_KH);
    __nv_bfloat16* sKl = (__nv_bfloat16*)(s_raw + OFF_KL);
    __nv_bfloat16* sVh = (__nv_bfloat16*)(s_raw + OFF_VH);
    __nv_bfloat16* sVl = (__nv_bfloat16*)(s_raw + OFF_VL);
    __nv_bfloat16* sQh = (__nv_bfloat16*)(s_raw + OFF_QH);
    __nv_bfloat16* sQl = (__nv_bfloat16*)(s_raw + OFF_QL);
    float*         rsarr = (float*)(s_raw + OFF_RS);
    float*         stg = (float*)s_raw;

    const int tid = threadIdx.x;
    const int w   = tid >> 5;
    const int ln  = tid & 31;
    const int qr  = ln >> 2;       // 0..7
    const int qc  = ln & 3;        // 0..3
    const int mb  = w & 3;         // m band: rows mb*32 .. +31 (2 m16 tiles)
    const int h   = w >> 2;        // key half: keys h*64 .. +63
    const int nb    = blockIdx.y;
    const int chunk = blockIdx.x;
    const int qbase = chunk * 128;

    // ---- stage Q (hi/lo), 128 rows x 32 ck, pitch 40 ----
    for (int f = tid; f < 512; f += 256) {
        int row = f >> 2, j = f & 3;
        const size_t src = ((size_t)(nb * LSEQ + qbase + row)) * CKD + j * 8;
        *(uint4*)(sQh + row * KPITCH + j * 8) = *(const uint4*)(g_qhi + src);
        *(uint4*)(sQl + row * KPITCH + j * 8) = *(const uint4*)(g_qlo + src);
    }

    float O0[8][4], O1[8][4];
#pragma unroll
    for (int v = 0; v < 8; v++)
#pragma unroll
        for (int j = 0; j < 4; j++) { O0[v][j] = 0.f; O1[v][j] = 0.f; }
    float rs00 = 0.f, rs01 = 0.f, rs10 = 0.f, rs11 = 0.f;

    // per-thread fragment bases
    const int kfb = (h * 64 + qr) * KPITCH + qc * 2;  // K B-frag base (bf16 idx)
    const int vfb = qr * VPITCH + h * 64 + qc * 2;    // V B-frag base
    const int qfb0 = (mb * 32 + qr) * KPITCH + qc * 2;        // Q mt0
    const int qfb1 = (mb * 32 + 16 + qr) * KPITCH + qc * 2;   // Q mt1

    for (int kt = 0; kt < 16; kt++) {
        __syncthreads();   // prior PV/frag reads finished before overwrite
        // ---- load K tile (hi/lo) ----
        for (int f = tid; f < 512; f += 256) {
            int row = f >> 2, j = f & 3;
            const size_t src = ((size_t)(nb * LSEQ + kt * 128 + row)) * CKD + j * 8;
            *(uint4*)(sKh + row * KPITCH + j * 8) = *(const uint4*)(g_khi + src);
            *(uint4*)(sKl + row * KPITCH + j * 8) = *(const uint4*)(g_klo + src);
        }
        // ---- load V tile (hi/lo): 64 cv rows x 128 keys ----
        for (int f = tid; f < 1024; f += 256) {
            int cv = f >> 4, j = f & 15;
            const size_t src = ((size_t)(nb * CVD + cv)) * LSEQ + kt * 128 + j * 8;
            *(uint4*)(sVh + cv * VPITCH + j * 8) = *(const uint4*)(g_vthi + src);
            *(uint4*)(sVl + cv * VPITCH + j * 8) = *(const uint4*)(g_vtlo + src);
        }
        __syncthreads();

        // ---- S = Q K^T : P[mt][n8][4] over this warp's 64-key half ----
        float P0[8][4], P1[8][4];
#pragma unroll
        for (int n = 0; n < 8; n++)
#pragma unroll
            for (int j = 0; j < 4; j++) { P0[n][j] = 0.f; P1[n][j] = 0.f; }

#pragma unroll
        for (int s = 0; s < 2; s++) {
            uint32_t Qh0[4], Ql0[4], Qh1[4], Ql1[4];
            const int qo0 = qfb0 + s * 16;
            const int qo1 = qfb1 + s * 16;
            Qh0[0] = ld32s(sQh + qo0);              Qh0[1] = ld32s(sQh + qo0 + 8 * KPITCH);
            Qh0[2] = ld32s(sQh + qo0 + 8);          Qh0[3] = ld32s(sQh + qo0 + 8 * KPITCH + 8);
            Ql0[0] = ld32s(sQl + qo0);              Ql0[1] = ld32s(sQl + qo0 + 8 * KPITCH);
            Ql0[2] = ld32s(sQl + qo0 + 8);          Ql0[3] = ld32s(sQl + qo0 + 8 * KPITCH + 8);
            Qh1[0] = ld32s(sQh + qo1);              Qh1[1] = ld32s(sQh + qo1 + 8 * KPITCH);
            Qh1[2] = ld32s(sQh + qo1 + 8);          Qh1[3] = ld32s(sQh + qo1 + 8 * KPITCH + 8);
            Ql1[0] = ld32s(sQl + qo1);              Ql1[1] = ld32s(sQl + qo1 + 8 * KPITCH);
            Ql1[2] = ld32s(sQl + qo1 + 8);          Ql1[3] = ld32s(sQl + qo1 + 8 * KPITCH + 8);
#pragma unroll
            for (int n = 0; n < 8; n++) {
                const int ko = kfb + n * 8 * KPITCH + s * 16;
                uint32_t bh0 = ld32s(sKh + ko), bh1 = ld32s(sKh + ko + 8);
                uint32_t bl0 = ld32s(sKl + ko), bl1 = ld32s(sKl + ko + 8);
                mma_bf16(P0[n], Qh0, bh0, bh1);
                mma_bf16(P0[n], Qh0, bl0, bl1);
                mma_bf16(P0[n], Ql0, bh0, bh1);
                mma_bf16(P1[n], Qh1, bh0, bh1);
                mma_bf16(P1[n], Qh1, bl0, bl1);
                mma_bf16(P1[n], Ql1, bh0, bh1);
            }
        }

        // ---- softmax numerator: p = exp2(s); accumulate row sums ----
#pragma unroll
        for (int n = 0; n < 8; n++) {
#pragma unroll
            for (int j = 0; j < 4; j++) { P0[n][j] = exp2f(P0[n][j]); P1[n][j] = exp2f(P1[n][j]); }
            rs00 += P0[n][0] + P0[n][1];
            rs01 += P0[n][2] + P0[n][3];
            rs10 += P1[n][0] + P1[n][1];
            rs11 += P1[n][2] + P1[n][3];
        }

        // ---- O += P V (P fragments built in-register, FA2 layout identity) ----
#pragma unroll
        for (int s = 0; s < 4; s++) {
            uint32_t Ah0[4], Al0[4], Ah1[4], Al1[4];
            const int t0 = 2 * s, t1 = 2 * s + 1;
            split2(P0[t0][0], P0[t0][1], Ah0[0], Al0[0]);
            split2(P0[t0][2], P0[t0][3], Ah0[1], Al0[1]);
            split2(P0[t1][0], P0[t1][1], Ah0[2], Al0[2]);
            split2(P0[t1][2], P0[t1][3], Ah0[3], Al0[3]);
            split2(P1[t0][0], P1[t0][1], Ah1[0], Al1[0]);
            split2(P1[t0][2], P1[t0][3], Ah1[1], Al1[1]);
            split2(P1[t1][0], P1[t1][1], Ah1[2], Al1[2]);
            split2(P1[t1][2], P1[t1][3], Ah1[3], Al1[3]);
#pragma unroll
            for (int v = 0; v < 8; v++) {
                const int vo = vfb + v * 8 * VPITCH + s * 16;
                uint32_t bh0 = ld32s(sVh + vo), bh1 = ld32s(sVh + vo + 8);
                uint32_t bl0 = ld32s(sVl + vo), bl1 = ld32s(sVl + vo + 8);
                mma_bf16(O0[v], Ah0, bh0, bh1);
                mma_bf16(O0[v], Ah0, bl0, bl1);
                mma_bf16(O0[v], Al0, bh0, bh1);
                mma_bf16(O1[v], Ah1, bh0, bh1);
                mma_bf16(O1[v], Ah1, bl0, bl1);
                mma_bf16(O1[v], Al1, bh0, bh1);
            }
        }
    }

    // ---- combine halves, normalize, scatter ----
    __syncthreads();
    // quad-reduce row sums (lanes sharing qr)
#pragma unroll
    for (int off = 1; off <= 2; off <<= 1) {
        rs00 += __shfl_xor_sync(0xffffffffu, rs00, off);
        rs01 += __shfl_xor_sync(0xffffffffu, rs01, off);
        rs10 += __shfl_xor_sync(0xffffffffu, rs10, off);
        rs11 += __shfl_xor_sync(0xffffffffu, rs11, off);
    }
    const int row0 = mb * 32 + qr;
    if (qc == 0) {
        rsarr[h * 128 + row0]      = rs00;
        rsarr[h * 128 + row0 + 8]  = rs01;
        rsarr[h * 128 + row0 + 16] = rs10;
        rsarr[h * 128 + row0 + 24] = rs11;
    }
    __syncthreads();   // also: all smem-tile reads done; staging overlay safe

    if (h == 0) {
#pragma unroll
        for (int v = 0; v < 8; v++) {
            int cv = v * 8 + qc * 2;
            *(float2*)&stg[(row0)      * STG_PITCH + cv] = make_float2(O0[v][0], O0[v][1]);
            *(float2*)&stg[(row0 + 8)  * STG_PITCH + cv] = make_float2(O0[v][2], O0[v][3]);
            *(float2*)&stg[(row0 + 16) * STG_PITCH + cv] = make_float2(O1[v][0], O1[v][1]);
            *(float2*)&stg[(row0 + 24) * STG_PITCH + cv] = make_float2(O1[v][2], O1[v][3]);
        }
    }
    __syncthreads();
    if (h == 1) {
#pragma unroll
        for (int v = 0; v < 8; v++) {
            int cv = v * 8 + qc * 2;
            float2* p;
            p = (float2*)&stg[(row0)      * STG_PITCH + cv]; p->x += O0[v][0]; p->y += O0[v][1];
            p = (float2*)&stg[(row0 + 8)  * STG_PITCH + cv]; p->x += O0[v][2]; p->y += O0[v][3];
            p = (float2*)&stg[(row0 + 16) * STG_PITCH + cv]; p->x += O1[v][0]; p->y += O1[v][1];
            p = (float2*)&stg[(row0 + 24) * STG_PITCH + cv]; p->x += O1[v][2]; p->y += O1[v][3];
        }
    }
    __syncthreads();
    if (tid < 128) {
        float sum = rsarr[tid] + rsarr[128 + tid];
        rsarr[tid] = 1.0f / sum;
    }
    __syncthreads();

    const int n = nb >> 2, b = nb & 3;
    const int bi = b >> 1, bj = b & 1;
    for (int e = tid; e < 8192; e += 256) {
        int wl   = e & 31;
        int side = (e >> 5) & 1;
        int hlo  = (e >> 6) & 1;
        int cv   = e >> 7;
        int ll   = hlo * 64 + wl * 2 + side;
        int hh   = bi * 32 + chunk * 2 + hlo;
        int w2   = side * 64 + bj * 32 + wl;
        out[(((size_t)(n * 64 + cv)) * 64 + hh) * 128 + w2] =
            stg[ll * STG_PITCH + cv] * rsarr[ll];
    }
}

// ---------------------------------------------------------------- launch
extern "C" void kernel_launch(void* const* d_in, const int* in_sizes, int n_in,
                              void* d_out, int out_size)
{
    (void)in_sizes; (void)n_in; (void)out_size;
    const float* x     = (const float*)d_in[0];
    const float* Wq    = (const float*)d_in[1];
    const float* bq    = (const float*)d_in[2];
    const float* gq    = (const float*)d_in[3];
    const float* betaq = (const float*)d_in[4];
    const float* Wk    = (const float*)d_in[5];
    const float* bk    = (const float*)d_in[6];
    const float* gk    = (const float*)d_in[7];
    const float* betak = (const float*)d_in[8];
    const float* Wv    = (const float*)d_in[9];
    const float* bv    = (const float*)d_in[10];
    float* out = (float*)d_out;

    cudaFuncSetAttribute(attn_kernel, cudaFuncAttributeMaxDynamicSharedMemorySize,
                         SMEM_BYTES);

    zero_stats_kernel<<<1, 64>>>();
    conv_kernel<<<1024, 128>>>(x, Wq, bq, Wk, bk, Wv, bv);
    bn_kernel<<<1, 64>>>(gq, betaq, gk, betak);
    prep_qk_kernel<<<8192, 256>>>();
    prep_v_kernel<<<8192, 256>>>();
    attn_kernel<<<dim3(16, 16), 256, SMEM_BYTES>>>(out);
}

// round 4
// speedup vs baseline: 2.6521x; 1.2577x over previous
#include <cuda_runtime.h>
#include <cuda_bf16.h>
#include <math.h>
#include <cstdint>

// ---------------------------------------------------------------- constants
#define NBLK  16
#define LSEQ  2048
#define CKD   32
#define CVD   64
#define NPOSF 32768.0f
#define EPSB  1e-5f
#define SCALE_Q 0.25505654350925196f   // (1/sqrt(32)) * log2(e)

// ---------------------------------------------------------------- scratch
__device__ float g_q [NBLK * LSEQ * CKD];
__device__ float g_k [NBLK * LSEQ * CKD];
__device__ float g_vt[NBLK * CVD * LSEQ];           // [nb][cv][l]
__device__ __nv_bfloat16 g_qhi[NBLK * LSEQ * CKD];
__device__ __nv_bfloat16 g_qlo[NBLK * LSEQ * CKD];
__device__ __nv_bfloat16 g_khi[NBLK * LSEQ * CKD];
__device__ __nv_bfloat16 g_klo[NBLK * LSEQ * CKD];
__device__ __nv_bfloat16 g_vthi[NBLK * CVD * LSEQ];
__device__ __nv_bfloat16 g_vtlo[NBLK * CVD * LSEQ];
__device__ float g_sum[64], g_sq[64], g_affa[64], g_affc[64];

// ---------------------------------------------------------------- helpers
__device__ __forceinline__ void mma_bf16(float* c, const uint32_t* a,
                                         uint32_t b0, uint32_t b1) {
    asm volatile(
        "mma.sync.aligned.m16n8k16.row.col.f32.bf16.bf16.f32 "
        "{%0,%1,%2,%3}, {%4,%5,%6,%7}, {%8,%9}, {%0,%1,%2,%3};"
        : "+f"(c[0]), "+f"(c[1]), "+f"(c[2]), "+f"(c[3])
        : "r"(a[0]), "r"(a[1]), "r"(a[2]), "r"(a[3]), "r"(b0), "r"(b1));
}
__device__ __forceinline__ uint32_t pack_bf16x2(float lo, float hi) {
    uint32_t r;
    asm("cvt.rn.bf16x2.f32 %0, %1, %2;" : "=r"(r) : "f"(hi), "f"(lo));
    return r;
}
__device__ __forceinline__ void split2(float p0, float p1, uint32_t& hw, uint32_t& lw) {
    hw = pack_bf16x2(p0, p1);
    float h0 = __uint_as_float(hw << 16);
    float h1 = __uint_as_float(hw & 0xffff0000u);
    lw = pack_bf16x2(p0 - h0, p1 - h1);
}
#define LDSM_X4(r0, r1, r2, r3, addr) \
    asm volatile("ldmatrix.sync.aligned.m8n8.x4.shared.b16 {%0,%1,%2,%3}, [%4];" \
        : "=r"(r0), "=r"(r1), "=r"(r2), "=r"(r3) : "r"(addr))
#define CP_ASYNC16(dst, src) \
    asm volatile("cp.async.cg.shared.global [%0], [%1], 16;" :: "r"(dst), "l"(src) : "memory")
#define CP_COMMIT() asm volatile("cp.async.commit_group;" ::: "memory")
#define CP_WAIT0()  asm volatile("cp.async.wait_group 0;" ::: "memory")

__device__ __forceinline__ uint32_t smem_u32(const void* p) {
    uint32_t a;
    asm("{ .reg .u64 t; cvta.to.shared.u64 t, %1; cvt.u32.u64 %0, t; }" : "=r"(a) : "l"(p));
    return a;
}

// ---------------------------------------------------------------- kernel 0
__global__ void zero_stats_kernel() { g_sum[threadIdx.x] = 0.f; g_sq[threadIdx.x] = 0.f; }

// ---------------------------------------------------------------- kernel 1: conv1x1
__global__ __launch_bounds__(128) void conv_kernel(
    const float* __restrict__ x,
    const float* __restrict__ Wq, const float* __restrict__ bq,
    const float* __restrict__ Wk, const float* __restrict__ bk,
    const float* __restrict__ Wv, const float* __restrict__ bv)
{
    __shared__ float xs[64 * 32];
    __shared__ float wsm[128 * 65];
    const int tid = threadIdx.x;
    const int p0  = blockIdx.x * 32;
    const int n      = p0 >> 13;
    const int imgoff = p0 & 8191;

    const float* xbase = x + (size_t)n * 64 * 8192 + imgoff;
    for (int f = tid; f < 64 * 32; f += 128) {
        int c = f >> 5, pos = f & 31;
        xs[c * 32 + pos] = xbase[c * 8192 + pos];
    }
    for (int f = tid; f < 128 * 64; f += 128) {
        int o = f >> 6, c = f & 63;
        float w;
        if      (o < 32) w = Wq[o * 64 + c];
        else if (o < 64) w = Wk[(o - 32) * 64 + c];
        else             w = Wv[(o - 64) * 64 + c];
        wsm[o * 65 + c] = w;
    }
    __syncthreads();

    const int oc = tid;
    float bias;
    if      (oc < 32) bias = bq[oc];
    else if (oc < 64) bias = bk[oc - 32];
    else              bias = bv[oc - 64];

    float acc[32];
#pragma unroll
    for (int p = 0; p < 32; p++) acc[p] = bias;

    const float4* xs4 = (const float4*)xs;
#pragma unroll 8
    for (int c = 0; c < 64; c++) {
        float wv = wsm[oc * 65 + c];
#pragma unroll
        for (int p4 = 0; p4 < 8; p4++) {
            float4 xv = xs4[c * 8 + p4];
            acc[p4 * 4 + 0] += wv * xv.x;
            acc[p4 * 4 + 1] += wv * xv.y;
            acc[p4 * 4 + 2] += wv * xv.z;
            acc[p4 * 4 + 3] += wv * xv.w;
        }
    }

    float s = 0.f, sq = 0.f;
#pragma unroll
    for (int pp = 0; pp < 32; pp++) {
        int q    = imgoff + pp;
        int h    = q >> 7;
        int w2   = q & 127;
        int side = w2 >> 6;
        int w    = w2 & 63;
        int b    = ((h >> 5) << 1) | (w >> 5);
        int l    = ((((h & 31) << 5) | (w & 31)) << 1) | side;
        int nb   = (n << 2) | b;
        float v  = acc[pp];
        if      (oc < 32) g_q[(size_t)(nb * LSEQ + l) * CKD + oc]         = v;
        else if (oc < 64) g_k[(size_t)(nb * LSEQ + l) * CKD + (oc - 32)]  = v;
        else              g_vt[((size_t)nb * CVD + (oc - 64)) * LSEQ + l] = v;
        s += v; sq += v * v;
    }
    if (oc < 64) { atomicAdd(&g_sum[oc], s); atomicAdd(&g_sq[oc], sq); }
}

// ---------------------------------------------------------------- kernel 2: BN fold
__global__ void bn_kernel(const float* __restrict__ gq, const float* __restrict__ betaq,
                          const float* __restrict__ gk, const float* __restrict__ betak)
{
    int c = threadIdx.x;
    float mean = g_sum[c] / NPOSF;
    float var  = g_sq[c] / NPOSF - mean * mean;
    float gg   = (c < 32) ? gq[c]    : gk[c - 32];
    float be   = (c < 32) ? betaq[c] : betak[c - 32];
    float a    = gg * rsqrtf(var + EPSB);
    g_affa[c] = a;
    g_affc[c] = be - mean * a;
}

// ---------------------------------------------------------------- kernel 3: prep (merged)
__device__ __forceinline__ void split_bf(float y, __nv_bfloat16& h, __nv_bfloat16& l) {
    h = __float2bfloat16_rn(y);
    l = __float2bfloat16_rn(y - __bfloat162float(h));
}

__global__ __launch_bounds__(512) void prep_kernel() {
    int idx = blockIdx.x * 512 + threadIdx.x;       // 0 .. 4M-1
    if (idx < 2097152) {
        int which = idx >> 20;
        int i = idx & 1048575;
        int ck = i & 31;
        if (which == 0) {
            float y = (g_q[i] * g_affa[ck] + g_affc[ck]) * SCALE_Q;
            split_bf(y, g_qhi[i], g_qlo[i]);
        } else {
            float y = g_k[i] * g_affa[32 + ck] + g_affc[32 + ck];
            split_bf(y, g_khi[i], g_klo[i]);
        }
    } else {
        int i = idx - 2097152;
        split_bf(g_vt[i], g_vthi[i], g_vtlo[i]);
    }
}

// ---------------------------------------------------------------- attention
// smem byte layout (double-buffered K,V):
//  K buf b:  b*20480        (KH +0, KL +10240)  rows pitch 80B
//  V buf b:  40960+b*34816  (VH +0, VL +17408)  rows pitch 272B
//  Q:        110592         (QH +0, QL +10240)  pitch 80B
//  rs:       131072         (2*128 floats)
#define OFF_V0   40960
#define OFF_Q    110592
#define OFF_RS   131072
#define SMEM_BYTES 132096
#define STG_PITCH 66       // float staging overlays offset 0 at the end

extern __shared__ char s_raw[];

__global__ __launch_bounds__(512, 1) void attn_kernel(float* __restrict__ out)
{
    const uint32_t sb = smem_u32(s_raw);
    float* rsarr = (float*)(s_raw + OFF_RS);
    float* stg   = (float*)s_raw;

    const int tid = threadIdx.x;
    const int w   = tid >> 5;
    const int ln  = tid & 31;
    const int qr  = ln >> 2;
    const int qc  = ln & 3;
    const int mb  = w & 7;         // m band: rows mb*16 .. +15
    const int h   = w >> 3;        // key half
    const int nb    = blockIdx.y;
    const int chunk = blockIdx.x;
    const int qbase = chunk * 128;

    const int li   = ln & 7;
    const int tsel = ln >> 3;

    // per-thread ldmatrix base offsets (bytes, within region)
    const uint32_t kbase = (uint32_t)((h * 64 + (tsel >> 1) * 8 + li) * 80 + (tsel & 1) * 16);
    const uint32_t vbase = (uint32_t)(((tsel >> 1) * 8 + li) * 272 + (h * 64 + (tsel & 1) * 8) * 2);
    const uint32_t qfrag = (uint32_t)((mb * 16 + (tsel & 1) * 8 + li) * 80 + (tsel >> 1) * 16);

    // ---- stage Q (plain), issue K/V tile 0 via cp.async ----
    for (int f = tid; f < 1024; f += 512) {
        int half = f >> 9, row = (f & 511) >> 2, j = f & 3;
        const size_t src = ((size_t)(nb * LSEQ + qbase + row)) * CKD + j * 8;
        const __nv_bfloat16* g = half ? g_qlo : g_qhi;
        *(uint4*)(s_raw + OFF_Q + half * 10240 + row * 80 + j * 16) = *(const uint4*)(g + src);
    }
    {
        const int buf = 0, kt = 0;
        for (int f = tid; f < 1024; f += 512) {
            int half = f >> 9, row = (f & 511) >> 2, j = f & 3;
            const __nv_bfloat16* g = half ? g_klo : g_khi;
            CP_ASYNC16(sb + buf * 20480 + half * 10240 + row * 80 + j * 16,
                       g + ((size_t)(nb * LSEQ + kt * 128 + row)) * CKD + j * 8);
        }
        for (int f = tid; f < 2048; f += 512) {
            int half = f >> 10, row = (f & 1023) >> 4, j = f & 15;
            const __nv_bfloat16* g = half ? g_vtlo : g_vthi;
            CP_ASYNC16(sb + OFF_V0 + buf * 34816 + half * 17408 + row * 272 + j * 16,
                       g + ((size_t)(nb * CVD + row)) * LSEQ + kt * 128 + j * 8);
        }
        CP_COMMIT();
    }
    __syncthreads();

    // ---- hoist Q fragments ----
    uint32_t Qh[2][4], Ql[2][4];
#pragma unroll
    for (int s = 0; s < 2; s++) {
        LDSM_X4(Qh[s][0], Qh[s][1], Qh[s][2], Qh[s][3], sb + OFF_Q + s * 32 + qfrag);
        LDSM_X4(Ql[s][0], Ql[s][1], Ql[s][2], Ql[s][3], sb + OFF_Q + 10240 + s * 32 + qfrag);
    }

    float O[8][4];
#pragma unroll
    for (int v = 0; v < 8; v++)
#pragma unroll
        for (int j = 0; j < 4; j++) O[v][j] = 0.f;
    float rs0 = 0.f, rs1 = 0.f;

    for (int kt = 0; kt < 16; kt++) {
        CP_WAIT0();
        __syncthreads();
        const uint32_t kB = sb + (kt & 1) * 20480;
        const uint32_t vB = sb + OFF_V0 + (kt & 1) * 34816;

        if (kt < 15) {
            const int buf = (kt + 1) & 1, nkt = kt + 1;
            for (int f = tid; f < 1024; f += 512) {
                int half = f >> 9, row = (f & 511) >> 2, j = f & 3;
                const __nv_bfloat16* g = half ? g_klo : g_khi;
                CP_ASYNC16(sb + buf * 20480 + half * 10240 + row * 80 + j * 16,
                           g + ((size_t)(nb * LSEQ + nkt * 128 + row)) * CKD + j * 8);
            }
            for (int f = tid; f < 2048; f += 512) {
                int half = f >> 10, row = (f & 1023) >> 4, j = f & 15;
                const __nv_bfloat16* g = half ? g_vtlo : g_vthi;
                CP_ASYNC16(sb + OFF_V0 + buf * 34816 + half * 17408 + row * 272 + j * 16,
                           g + ((size_t)(nb * CVD + row)) * LSEQ + nkt * 128 + j * 8);
            }
            CP_COMMIT();
        }

        // ---- S = Q K^T over this warp's 64-key half ----
        float P[8][4];
#pragma unroll
        for (int n = 0; n < 8; n++)
#pragma unroll
            for (int j = 0; j < 4; j++) P[n][j] = 0.f;

#pragma unroll
        for (int s = 0; s < 2; s++) {
#pragma unroll
            for (int i = 0; i < 4; i++) {
                const int np = 2 * i;
                uint32_t kh[4], kl[4];
                const uint32_t ko = np * 640 + s * 32 + kbase;
                LDSM_X4(kh[0], kh[1], kh[2], kh[3], kB + ko);
                LDSM_X4(kl[0], kl[1], kl[2], kl[3], kB + 10240 + ko);
                mma_bf16(P[np],     Qh[s], kh[0], kh[1]);
                mma_bf16(P[np],     Qh[s], kl[0], kl[1]);
                mma_bf16(P[np],     Ql[s], kh[0], kh[1]);
                mma_bf16(P[np + 1], Qh[s], kh[2], kh[3]);
                mma_bf16(P[np + 1], Qh[s], kl[2], kl[3]);
                mma_bf16(P[np + 1], Ql[s], kh[2], kh[3]);
            }
        }

        // ---- exp2 + row sums ----
#pragma unroll
        for (int n = 0; n < 8; n++) {
#pragma unroll
            for (int j = 0; j < 4; j++) P[n][j] = exp2f(P[n][j]);
            rs0 += P[n][0] + P[n][1];
            rs1 += P[n][2] + P[n][3];
        }

        // ---- O += P V (3-term, A-frags from P in-register) ----
#pragma unroll
        for (int s = 0; s < 4; s++) {
            uint32_t Ah[4], Al[4];
            const int t0 = 2 * s, t1 = 2 * s + 1;
            split2(P[t0][0], P[t0][1], Ah[0], Al[0]);
            split2(P[t0][2], P[t0][3], Ah[1], Al[1]);
            split2(P[t1][0], P[t1][1], Ah[2], Al[2]);
            split2(P[t1][2], P[t1][3], Ah[3], Al[3]);
#pragma unroll
            for (int i = 0; i < 4; i++) {
                const int vp = 2 * i;
                uint32_t vh[4], vl[4];
                const uint32_t vo = vp * 2176 + s * 32 + vbase;
                LDSM_X4(vh[0], vh[1], vh[2], vh[3], vB + vo);
                LDSM_X4(vl[0], vl[1], vl[2], vl[3], vB + 17408 + vo);
                mma_bf16(O[vp],     Ah, vh[0], vh[1]);
                mma_bf16(O[vp],     Ah, vl[0], vl[1]);
                mma_bf16(O[vp],     Al, vh[0], vh[1]);
                mma_bf16(O[vp + 1], Ah, vh[2], vh[3]);
                mma_bf16(O[vp + 1], Ah, vl[2], vl[3]);
                mma_bf16(O[vp + 1], Al, vh[2], vh[3]);
            }
        }
    }

    // ---- combine halves, normalize, scatter ----
    rs0 += __shfl_xor_sync(0xffffffffu, rs0, 1);
    rs0 += __shfl_xor_sync(0xffffffffu, rs0, 2);
    rs1 += __shfl_xor_sync(0xffffffffu, rs1, 1);
    rs1 += __shfl_xor_sync(0xffffffffu, rs1, 2);
    const int row0 = mb * 16 + qr;
    if (qc == 0) {
        rsarr[h * 128 + row0]     = rs0;
        rsarr[h * 128 + row0 + 8] = rs1;
    }
    __syncthreads();   // also: all smem-tile reads done; stg overlay safe

    if (h == 0) {
#pragma unroll
        for (int v = 0; v < 8; v++) {
            int cv = v * 8 + qc * 2;
            *(float2*)&stg[(row0)     * STG_PITCH + cv] = make_float2(O[v][0], O[v][1]);
            *(float2*)&stg[(row0 + 8) * STG_PITCH + cv] = make_float2(O[v][2], O[v][3]);
        }
    }
    __syncthreads();
    if (h == 1) {
#pragma unroll
        for (int v = 0; v < 8; v++) {
            int cv = v * 8 + qc * 2;
            float2* p;
            p = (float2*)&stg[(row0)     * STG_PITCH + cv]; p->x += O[v][0]; p->y += O[v][1];
            p = (float2*)&stg[(row0 + 8) * STG_PITCH + cv]; p->x += O[v][2]; p->y += O[v][3];
        }
    }
    __syncthreads();
    if (tid < 128) rsarr[tid] = 1.0f / (rsarr[tid] + rsarr[128 + tid]);
    __syncthreads();

    const int n = nb >> 2, b = nb & 3;
    const int bi = b >> 1, bj = b & 1;
    for (int e = tid; e < 8192; e += 512) {
        int wl   = e & 31;
        int side = (e >> 5) & 1;
        int hlo  = (e >> 6) & 1;
        int cv   = e >> 7;
        int ll   = hlo * 64 + wl * 2 + side;
        int hh   = bi * 32 + chunk * 2 + hlo;
        int w2   = side * 64 + bj * 32 + wl;
        out[(((size_t)(n * 64 + cv)) * 64 + hh) * 128 + w2] =
            stg[ll * STG_PITCH + cv] * rsarr[ll];
    }
}

// ---------------------------------------------------------------- launch
extern "C" void kernel_launch(void* const* d_in, const int* in_sizes, int n_in,
                              void* d_out, int out_size)
{
    (void)in_sizes; (void)n_in; (void)out_size;
    const float* x     = (const float*)d_in[0];
    const float* Wq    = (const float*)d_in[1];
    const float* bq    = (const float*)d_in[2];
    const float* gq    = (const float*)d_in[3];
    const float* betaq = (const float*)d_in[4];
    const float* Wk    = (const float*)d_in[5];
    const float* bk    = (const float*)d_in[6];
    const float* gk    = (const float*)d_in[7];
    const float* betak = (const float*)d_in[8];
    const float* Wv    = (const float*)d_in[9];
    const float* bv    = (const float*)d_in[10];
    float* out = (float*)d_out;

    cudaFuncSetAttribute(attn_kernel, cudaFuncAttributeMaxDynamicSharedMemorySize,
                         SMEM_BYTES);

    zero_stats_kernel<<<1, 64>>>();
    conv_kernel<<<1024, 128>>>(x, Wq, bq, Wk, bk, Wv, bv);
    bn_kernel<<<1, 64>>>(gq, betaq, gk, betak);
    prep_kernel<<<8192, 512>>>();
    attn_kernel<<<dim3(16, 16), 512, SMEM_BYTES>>>(out);
}

// round 5
// speedup vs baseline: 2.6719x; 1.0075x over previous
#include <cuda_runtime.h>
#include <cuda_bf16.h>
#include <math.h>
#include <cstdint>

// ---------------------------------------------------------------- constants
#define NBLK  16
#define LSEQ  2048
#define CKD   32
#define CVD   64
#define NPOSF 32768.0f
#define EPSB  1e-5f
#define SCALE_Q 0.25505654350925196f   // (1/sqrt(32)) * log2(e)

// ---------------------------------------------------------------- scratch
__device__ float g_q [NBLK * LSEQ * CKD];
__device__ float g_k [NBLK * LSEQ * CKD];
__device__ float g_vt[NBLK * CVD * LSEQ];           // [nb][cv][l]
__device__ __nv_bfloat16 g_qhi[NBLK * LSEQ * CKD];
__device__ __nv_bfloat16 g_qlo[NBLK * LSEQ * CKD];
__device__ __nv_bfloat16 g_khi[NBLK * LSEQ * CKD];
__device__ __nv_bfloat16 g_klo[NBLK * LSEQ * CKD];
__device__ __nv_bfloat16 g_vthi[NBLK * CVD * LSEQ];
__device__ __nv_bfloat16 g_vtlo[NBLK * CVD * LSEQ];
__device__ float g_sum[64], g_sq[64], g_affa[64], g_affc[64];

// ---------------------------------------------------------------- helpers
__device__ __forceinline__ void mma_bf16(float* c, const uint32_t* a,
                                         uint32_t b0, uint32_t b1) {
    asm volatile(
        "mma.sync.aligned.m16n8k16.row.col.f32.bf16.bf16.f32 "
        "{%0,%1,%2,%3}, {%4,%5,%6,%7}, {%8,%9}, {%0,%1,%2,%3};"
        : "+f"(c[0]), "+f"(c[1]), "+f"(c[2]), "+f"(c[3])
        : "r"(a[0]), "r"(a[1]), "r"(a[2]), "r"(a[3]), "r"(b0), "r"(b1));
}
__device__ __forceinline__ uint32_t pack_bf16x2(float lo, float hi) {
    uint32_t r;
    asm("cvt.rn.bf16x2.f32 %0, %1, %2;" : "=r"(r) : "f"(hi), "f"(lo));
    return r;
}
__device__ __forceinline__ void split2(float p0, float p1, uint32_t& hw, uint32_t& lw) {
    hw = pack_bf16x2(p0, p1);
    float h0 = __uint_as_float(hw << 16);
    float h1 = __uint_as_float(hw & 0xffff0000u);
    lw = pack_bf16x2(p0 - h0, p1 - h1);
}
#define LDSM_X4(r0, r1, r2, r3, addr) \
    asm volatile("ldmatrix.sync.aligned.m8n8.x4.shared.b16 {%0,%1,%2,%3}, [%4];" \
        : "=r"(r0), "=r"(r1), "=r"(r2), "=r"(r3) : "r"(addr))
#define CP_ASYNC16(dst, src) \
    asm volatile("cp.async.cg.shared.global [%0], [%1], 16;" :: "r"(dst), "l"(src) : "memory")
#define CP_COMMIT() asm volatile("cp.async.commit_group;" ::: "memory")
#define CP_WAIT0()  asm volatile("cp.async.wait_group 0;" ::: "memory")

__device__ __forceinline__ uint32_t smem_u32(const void* p) {
    uint32_t a;
    asm("{ .reg .u64 t; cvta.to.shared.u64 t, %1; cvt.u32.u64 %0, t; }" : "=r"(a) : "l"(p));
    return a;
}

// ---------------------------------------------------------------- kernel 0
__global__ void zero_stats_kernel() { g_sum[threadIdx.x] = 0.f; g_sq[threadIdx.x] = 0.f; }

// ---------------------------------------------------------------- kernel 1: conv1x1
__global__ __launch_bounds__(128) void conv_kernel(
    const float* __restrict__ x,
    const float* __restrict__ Wq, const float* __restrict__ bq,
    const float* __restrict__ Wk, const float* __restrict__ bk,
    const float* __restrict__ Wv, const float* __restrict__ bv)
{
    __shared__ float xs[64 * 32];
    __shared__ float wsm[128 * 65];
    const int tid = threadIdx.x;
    const int p0  = blockIdx.x * 32;
    const int n      = p0 >> 13;
    const int imgoff = p0 & 8191;

    const float* xbase = x + (size_t)n * 64 * 8192 + imgoff;
    for (int f = tid; f < 64 * 32; f += 128) {
        int c = f >> 5, pos = f & 31;
        xs[c * 32 + pos] = xbase[c * 8192 + pos];
    }
    for (int f = tid; f < 128 * 64; f += 128) {
        int o = f >> 6, c = f & 63;
        float w;
        if      (o < 32) w = Wq[o * 64 + c];
        else if (o < 64) w = Wk[(o - 32) * 64 + c];
        else             w = Wv[(o - 64) * 64 + c];
        wsm[o * 65 + c] = w;
    }
    __syncthreads();

    const int oc = tid;
    float bias;
    if      (oc < 32) bias = bq[oc];
    else if (oc < 64) bias = bk[oc - 32];
    else              bias = bv[oc - 64];

    float acc[32];
#pragma unroll
    for (int p = 0; p < 32; p++) acc[p] = bias;

    const float4* xs4 = (const float4*)xs;
#pragma unroll 8
    for (int c = 0; c < 64; c++) {
        float wv = wsm[oc * 65 + c];
#pragma unroll
        for (int p4 = 0; p4 < 8; p4++) {
            float4 xv = xs4[c * 8 + p4];
            acc[p4 * 4 + 0] += wv * xv.x;
            acc[p4 * 4 + 1] += wv * xv.y;
            acc[p4 * 4 + 2] += wv * xv.z;
            acc[p4 * 4 + 3] += wv * xv.w;
        }
    }

    float s = 0.f, sq = 0.f;
#pragma unroll
    for (int pp = 0; pp < 32; pp++) {
        int q    = imgoff + pp;
        int h    = q >> 7;
        int w2   = q & 127;
        int side = w2 >> 6;
        int w    = w2 & 63;
        int b    = ((h >> 5) << 1) | (w >> 5);
        int l    = ((((h & 31) << 5) | (w & 31)) << 1) | side;
        int nb   = (n << 2) | b;
        float v  = acc[pp];
        if      (oc < 32) g_q[(size_t)(nb * LSEQ + l) * CKD + oc]         = v;
        else if (oc < 64) g_k[(size_t)(nb * LSEQ + l) * CKD + (oc - 32)]  = v;
        else              g_vt[((size_t)nb * CVD + (oc - 64)) * LSEQ + l] = v;
        s += v; sq += v * v;
    }
    if (oc < 64) { atomicAdd(&g_sum[oc], s); atomicAdd(&g_sq[oc], sq); }
}

// ---------------------------------------------------------------- kernel 2: BN fold
__global__ void bn_kernel(const float* __restrict__ gq, const float* __restrict__ betaq,
                          const float* __restrict__ gk, const float* __restrict__ betak)
{
    int c = threadIdx.x;
    float mean = g_sum[c] / NPOSF;
    float var  = g_sq[c] / NPOSF - mean * mean;
    float gg   = (c < 32) ? gq[c]    : gk[c - 32];
    float be   = (c < 32) ? betaq[c] : betak[c - 32];
    float a    = gg * rsqrtf(var + EPSB);
    g_affa[c] = a;
    g_affc[c] = be - mean * a;
}

// ---------------------------------------------------------------- kernel 3: prep (2 elems/thread)
__global__ __launch_bounds__(256) void prep_kernel() {
    int idx = blockIdx.x * 256 + threadIdx.x;       // 0 .. 2M-1 (pairs)
    if (idx < 1048576) {
        int which = idx >> 19;                      // 0: q, 1: k
        int i = (idx & 524287) * 2;
        int ck = i & 31;
        const float* src = which ? g_k : g_q;
        float2 rv = *(const float2*)(src + i);
        int base = which ? 32 : 0;
        float a0 = g_affa[base + ck],     c0 = g_affc[base + ck];
        float a1 = g_affa[base + ck + 1], c1 = g_affc[base + ck + 1];
        float y0 = rv.x * a0 + c0;
        float y1 = rv.y * a1 + c1;
        if (!which) { y0 *= SCALE_Q; y1 *= SCALE_Q; }
        uint32_t hw, lw;
        split2(y0, y1, hw, lw);
        int o = i >> 1;
        if (which) {
            ((uint32_t*)g_khi)[o] = hw; ((uint32_t*)g_klo)[o] = lw;
        } else {
            ((uint32_t*)g_qhi)[o] = hw; ((uint32_t*)g_qlo)[o] = lw;
        }
    } else {
        int i = (idx - 1048576) * 2;
        float2 rv = *(const float2*)(g_vt + i);
        uint32_t hw, lw;
        split2(rv.x, rv.y, hw, lw);
        int o = i >> 1;
        ((uint32_t*)g_vthi)[o] = hw; ((uint32_t*)g_vtlo)[o] = lw;
    }
}

// ---------------------------------------------------------------- attention
// smem byte layout (double-buffered K,V):
//  K buf b:  b*20480        (KH +0, KL +10240)  rows pitch 80B
//  V buf b:  40960+b*34816  (VH +0, VL +17408)  rows pitch 272B
//  Q:        110592         (QH +0, QL +10240)  pitch 80B
//  rs:       131072         (2*128 floats)
#define OFF_V0   40960
#define OFF_Q    110592
#define OFF_RS   131072
#define SMEM_BYTES 132096
#define STG_PITCH 66       // float staging overlays offset 0 at the end

extern __shared__ char s_raw[];

__global__ __launch_bounds__(512, 1) void attn_kernel(float* __restrict__ out)
{
    const uint32_t sb = smem_u32(s_raw);
    float* rsarr = (float*)(s_raw + OFF_RS);
    float* stg   = (float*)s_raw;

    const int tid = threadIdx.x;
    const int w   = tid >> 5;
    const int ln  = tid & 31;
    const int qr  = ln >> 2;
    const int qc  = ln & 3;
    const int mb  = w & 7;         // m band: rows mb*16 .. +15
    const int h   = w >> 3;        // key half
    const int nb    = blockIdx.y;
    const int chunk = blockIdx.x;
    const int qbase = chunk * 128;

    const int li   = ln & 7;
    const int tsel = ln >> 3;

    // per-thread ldmatrix base offsets (bytes, within region)
    const uint32_t kbase = (uint32_t)((h * 64 + (tsel >> 1) * 8 + li) * 80 + (tsel & 1) * 16);
    const uint32_t vbase = (uint32_t)(((tsel >> 1) * 8 + li) * 272 + (h * 64 + (tsel & 1) * 8) * 2);
    const uint32_t qfrag = (uint32_t)((mb * 16 + (tsel & 1) * 8 + li) * 80 + (tsel >> 1) * 16);

    // ---- stage Q (plain), issue K/V tile 0 via cp.async ----
    for (int f = tid; f < 1024; f += 512) {
        int half = f >> 9, row = (f & 511) >> 2, j = f & 3;
        const size_t src = ((size_t)(nb * LSEQ + qbase + row)) * CKD + j * 8;
        const __nv_bfloat16* g = half ? g_qlo : g_qhi;
        *(uint4*)(s_raw + OFF_Q + half * 10240 + row * 80 + j * 16) = *(const uint4*)(g + src);
    }
    {
        const int buf = 0, kt = 0;
        for (int f = tid; f < 1024; f += 512) {
            int half = f >> 9, row = (f & 511) >> 2, j = f & 3;
            const __nv_bfloat16* g = half ? g_klo : g_khi;
            CP_ASYNC16(sb + buf * 20480 + half * 10240 + row * 80 + j * 16,
                       g + ((size_t)(nb * LSEQ + kt * 128 + row)) * CKD + j * 8);
        }
        for (int f = tid; f < 2048; f += 512) {
            int half = f >> 10, row = (f & 1023) >> 4, j = f & 15;
            const __nv_bfloat16* g = half ? g_vtlo : g_vthi;
            CP_ASYNC16(sb + OFF_V0 + buf * 34816 + half * 17408 + row * 272 + j * 16,
                       g + ((size_t)(nb * CVD + row)) * LSEQ + kt * 128 + j * 8);
        }
        CP_COMMIT();
    }
    __syncthreads();

    // ---- hoist Q fragments ----
    uint32_t Qh[2][4], Ql[2][4];
#pragma unroll
    for (int s = 0; s < 2; s++) {
        LDSM_X4(Qh[s][0], Qh[s][1], Qh[s][2], Qh[s][3], sb + OFF_Q + s * 32 + qfrag);
        LDSM_X4(Ql[s][0], Ql[s][1], Ql[s][2], Ql[s][3], sb + OFF_Q + 10240 + s * 32 + qfrag);
    }

    float O[8][4];
#pragma unroll
    for (int v = 0; v < 8; v++)
#pragma unroll
        for (int j = 0; j < 4; j++) O[v][j] = 0.f;
    float rs0 = 0.f, rs1 = 0.f;

    for (int kt = 0; kt < 16; kt++) {
        CP_WAIT0();
        __syncthreads();
        const uint32_t kB = sb + (kt & 1) * 20480;
        const uint32_t vB = sb + OFF_V0 + (kt & 1) * 34816;

        if (kt < 15) {
            const int buf = (kt + 1) & 1, nkt = kt + 1;
            for (int f = tid; f < 1024; f += 512) {
                int half = f >> 9, row = (f & 511) >> 2, j = f & 3;
                const __nv_bfloat16* g = half ? g_klo : g_khi;
                CP_ASYNC16(sb + buf * 20480 + half * 10240 + row * 80 + j * 16,
                           g + ((size_t)(nb * LSEQ + nkt * 128 + row)) * CKD + j * 8);
            }
            for (int f = tid; f < 2048; f += 512) {
                int half = f >> 10, row = (f & 1023) >> 4, j = f & 15;
                const __nv_bfloat16* g = half ? g_vtlo : g_vthi;
                CP_ASYNC16(sb + OFF_V0 + buf * 34816 + half * 17408 + row * 272 + j * 16,
                           g + ((size_t)(nb * CVD + row)) * LSEQ + nkt * 128 + j * 8);
            }
            CP_COMMIT();
        }

        // ---- fused per key-pair (16 keys): S mma -> exp2 -> split -> PV mma ----
#pragma unroll
        for (int t = 0; t < 4; t++) {
            float P0[4] = {0.f, 0.f, 0.f, 0.f};
            float P1[4] = {0.f, 0.f, 0.f, 0.f};
#pragma unroll
            for (int s = 0; s < 2; s++) {
                uint32_t kh[4], kl[4];
                const uint32_t ko = t * 1280 + s * 32 + kbase;
                LDSM_X4(kh[0], kh[1], kh[2], kh[3], kB + ko);
                LDSM_X4(kl[0], kl[1], kl[2], kl[3], kB + 10240 + ko);
                mma_bf16(P0, Qh[s], kh[0], kh[1]);
                mma_bf16(P0, Qh[s], kl[0], kl[1]);
                mma_bf16(P0, Ql[s], kh[0], kh[1]);
                mma_bf16(P1, Qh[s], kh[2], kh[3]);
                mma_bf16(P1, Qh[s], kl[2], kl[3]);
                mma_bf16(P1, Ql[s], kh[2], kh[3]);
            }

#pragma unroll
            for (int j = 0; j < 4; j++) { P0[j] = exp2f(P0[j]); P1[j] = exp2f(P1[j]); }
            rs0 += P0[0] + P0[1] + P1[0] + P1[1];
            rs1 += P0[2] + P0[3] + P1[2] + P1[3];

            uint32_t Ah[4], Al[4];
            split2(P0[0], P0[1], Ah[0], Al[0]);
            split2(P0[2], P0[3], Ah[1], Al[1]);
            split2(P1[0], P1[1], Ah[2], Al[2]);
            split2(P1[2], P1[3], Ah[3], Al[3]);

#pragma unroll
            for (int i = 0; i < 4; i++) {
                const int vp = 2 * i;
                uint32_t vh[4], vl[4];
                const uint32_t vo = vp * 2176 + t * 32 + vbase;
                LDSM_X4(vh[0], vh[1], vh[2], vh[3], vB + vo);
                LDSM_X4(vl[0], vl[1], vl[2], vl[3], vB + 17408 + vo);
                mma_bf16(O[vp],     Ah, vh[0], vh[1]);
                mma_bf16(O[vp],     Ah, vl[0], vl[1]);
                mma_bf16(O[vp],     Al, vh[0], vh[1]);
                mma_bf16(O[vp + 1], Ah, vh[2], vh[3]);
                mma_bf16(O[vp + 1], Ah, vl[2], vl[3]);
                mma_bf16(O[vp + 1], Al, vh[2], vh[3]);
            }
        }
    }

    // ---- combine halves, normalize, scatter ----
    rs0 += __shfl_xor_sync(0xffffffffu, rs0, 1);
    rs0 += __shfl_xor_sync(0xffffffffu, rs0, 2);
    rs1 += __shfl_xor_sync(0xffffffffu, rs1, 1);
    rs1 += __shfl_xor_sync(0xffffffffu, rs1, 2);
    const int row0 = mb * 16 + qr;
    if (qc == 0) {
        rsarr[h * 128 + row0]     = rs0;
        rsarr[h * 128 + row0 + 8] = rs1;
    }
    __syncthreads();   // all smem-tile reads done; stg overlay safe

    if (h == 0) {
#pragma unroll
        for (int v = 0; v < 8; v++) {
            int cv = v * 8 + qc * 2;
            *(float2*)&stg[(row0)     * STG_PITCH + cv] = make_float2(O[v][0], O[v][1]);
            *(float2*)&stg[(row0 + 8) * STG_PITCH + cv] = make_float2(O[v][2], O[v][3]);
        }
    }
    __syncthreads();
    if (h == 1) {
#pragma unroll
        for (int v = 0; v < 8; v++) {
            int cv = v * 8 + qc * 2;
            float2* p;
            p = (float2*)&stg[(row0)     * STG_PITCH + cv]; p->x += O[v][0]; p->y += O[v][1];
            p = (float2*)&stg[(row0 + 8) * STG_PITCH + cv]; p->x += O[v][2]; p->y += O[v][3];
        }
    }
    __syncthreads();
    if (tid < 128) rsarr[tid] = 1.0f / (rsarr[tid] + rsarr[128 + tid]);
    __syncthreads();

    const int n = nb >> 2, b = nb & 3;
    const int bi = b >> 1, bj = b & 1;
    for (int e = tid; e < 8192; e += 512) {
        int wl   = e & 31;
        int side = (e >> 5) & 1;
        int hlo  = (e >> 6) & 1;
        int cv   = e >> 7;
        int ll   = hlo * 64 + wl * 2 + side;
        int hh   = bi * 32 + chunk * 2 + hlo;
        int w2   = side * 64 + bj * 32 + wl;
        out[(((size_t)(n * 64 + cv)) * 64 + hh) * 128 + w2] =
            stg[ll * STG_PITCH + cv] * rsarr[ll];
    }
}

// ---------------------------------------------------------------- launch
extern "C" void kernel_launch(void* const* d_in, const int* in_sizes, int n_in,
                              void* d_out, int out_size)
{
    (void)in_sizes; (void)n_in; (void)out_size;
    const float* x     = (const float*)d_in[0];
    const float* Wq    = (const float*)d_in[1];
    const float* bq    = (const float*)d_in[2];
    const float* gq    = (const float*)d_in[3];
    const float* betaq = (const float*)d_in[4];
    const float* Wk    = (const float*)d_in[5];
    const float* bk    = (const float*)d_in[6];
    const float* gk    = (const float*)d_in[7];
    const float* betak = (const float*)d_in[8];
    const float* Wv    = (const float*)d_in[9];
    const float* bv    = (const float*)d_in[10];
    float* out = (float*)d_out;

    cudaFuncSetAttribute(attn_kernel, cudaFuncAttributeMaxDynamicSharedMemorySize,
                         SMEM_BYTES);

    zero_stats_kernel<<<1, 64>>>();
    conv_kernel<<<1024, 128>>>(x, Wq, bq, Wk, bk, Wv, bv);
    bn_kernel<<<1, 64>>>(gq, betaq, gk, betak);
    prep_kernel<<<8192, 256>>>();
    attn_kernel<<<dim3(16, 16), 512, SMEM_BYTES>>>(out);
}

// round 6
// speedup vs baseline: 2.9864x; 1.1177x over previous
#include <cuda_runtime.h>
#include <cuda_bf16.h>
#include <math.h>
#include <cstdint>

// ---------------------------------------------------------------- constants
#define NBLK  16
#define LSEQ  2048
#define CKD   32
#define CVD   64
#define NPOSF 32768.0f
#define EPSB  1e-5f
#define SCALE_Q 0.25505654350925196f   // (1/sqrt(32)) * log2(e)

// per-(nb,kt) staged tile blob: [Khi 10240 | Klo 10240 | Vhi 17408 | Vlo 17408]
#define TILE_BYTES 55296
#define BLOB_K_LO  10240
#define BLOB_V_HI  20480
#define BLOB_V_LO  37888

// ---------------------------------------------------------------- scratch
__device__ float g_q [NBLK * LSEQ * CKD];
__device__ float g_k [NBLK * LSEQ * CKD];
__device__ float g_vt[NBLK * CVD * LSEQ];           // [nb][cv][l]
__device__ __nv_bfloat16 g_qhi[NBLK * LSEQ * CKD];
__device__ __nv_bfloat16 g_qlo[NBLK * LSEQ * CKD];
__device__ __align__(128) unsigned char g_tiles[NBLK * 16 * TILE_BYTES];
__device__ float g_sum[64], g_sq[64];

// ---------------------------------------------------------------- helpers
__device__ __forceinline__ void mma_bf16(float* c, const uint32_t* a,
                                         uint32_t b0, uint32_t b1) {
    asm volatile(
        "mma.sync.aligned.m16n8k16.row.col.f32.bf16.bf16.f32 "
        "{%0,%1,%2,%3}, {%4,%5,%6,%7}, {%8,%9}, {%0,%1,%2,%3};"
        : "+f"(c[0]), "+f"(c[1]), "+f"(c[2]), "+f"(c[3])
        : "r"(a[0]), "r"(a[1]), "r"(a[2]), "r"(a[3]), "r"(b0), "r"(b1));
}
__device__ __forceinline__ uint32_t pack_bf16x2(float lo, float hi) {
    uint32_t r;
    asm("cvt.rn.bf16x2.f32 %0, %1, %2;" : "=r"(r) : "f"(hi), "f"(lo));
    return r;
}
__device__ __forceinline__ void split2(float p0, float p1, uint32_t& hw, uint32_t& lw) {
    hw = pack_bf16x2(p0, p1);
    float h0 = __uint_as_float(hw << 16);
    float h1 = __uint_as_float(hw & 0xffff0000u);
    lw = pack_bf16x2(p0 - h0, p1 - h1);
}
#define LDSM_X4(r0, r1, r2, r3, addr) \
    asm volatile("ldmatrix.sync.aligned.m8n8.x4.shared.b16 {%0,%1,%2,%3}, [%4];" \
        : "=r"(r0), "=r"(r1), "=r"(r2), "=r"(r3) : "r"(addr))

#define MBARRIER_INIT(mb, cnt) \
    asm volatile("mbarrier.init.shared.b64 [%0], %1;" :: "r"((uint32_t)(mb)), "r"((uint32_t)(cnt)) : "memory")
#define MBARRIER_EXPECT_TX(mb, bytes) \
    asm volatile("mbarrier.arrive.expect_tx.shared.b64 _, [%0], %1;" :: "r"((uint32_t)(mb)), "r"((uint32_t)(bytes)) : "memory")
#define CP_BULK(dst, src, bytes, mbar) \
    asm volatile("cp.async.bulk.shared::cta.global.mbarrier::complete_tx::bytes [%0], [%1], %2, [%3];" \
                 :: "r"((uint32_t)(dst)), "l"(src), "r"((uint32_t)(bytes)), "r"((uint32_t)(mbar)) : "memory")
#define MBARRIER_WAIT_PARITY(mb, par) do {                                          \
    uint32_t _mbar = (uint32_t)(mb); uint32_t _par = (uint32_t)(par); uint32_t _done;\
    asm volatile("{\n\t.reg .pred p;\n\t"                                           \
        "mbarrier.try_wait.parity.acquire.cta.shared::cta.b64 p, [%1], %2;\n\t"     \
        "selp.b32 %0, 1, 0, p;\n\t}" : "=r"(_done) : "r"(_mbar), "r"(_par) : "memory"); \
    if (!_done) {                                                                   \
        asm volatile("{\n\t.reg .pred P1;\n\t"                                      \
            "WAIT_LOOP_%=:\n\t"                                                     \
            "mbarrier.try_wait.parity.acquire.cta.shared::cta.b64 P1, [%0], %1, 0x989680;\n\t" \
            "@P1 bra.uni WAIT_DONE_%=;\n\t"                                         \
            "bra.uni WAIT_LOOP_%=;\n\t"                                             \
            "WAIT_DONE_%=:\n\t}" :: "r"(_mbar), "r"(_par) : "memory");              \
    } } while (0)

__device__ __forceinline__ uint32_t smem_u32(const void* p) {
    uint32_t a;
    asm("{ .reg .u64 t; cvta.to.shared.u64 t, %1; cvt.u32.u64 %0, t; }" : "=r"(a) : "l"(p));
    return a;
}

// ---------------------------------------------------------------- kernel 0
__global__ void zero_stats_kernel() { g_sum[threadIdx.x] = 0.f; g_sq[threadIdx.x] = 0.f; }

// ---------------------------------------------------------------- kernel 1: conv1x1
__global__ __launch_bounds__(128) void conv_kernel(
    const float* __restrict__ x,
    const float* __restrict__ Wq, const float* __restrict__ bq,
    const float* __restrict__ Wk, const float* __restrict__ bk,
    const float* __restrict__ Wv, const float* __restrict__ bv)
{
    __shared__ float xs[64 * 32];
    __shared__ float wsm[128 * 65];
    const int tid = threadIdx.x;
    const int p0  = blockIdx.x * 32;
    const int n      = p0 >> 13;
    const int imgoff = p0 & 8191;

    const float* xbase = x + (size_t)n * 64 * 8192 + imgoff;
    for (int f = tid; f < 64 * 32; f += 128) {
        int c = f >> 5, pos = f & 31;
        xs[c * 32 + pos] = xbase[c * 8192 + pos];
    }
    for (int f = tid; f < 128 * 64; f += 128) {
        int o = f >> 6, c = f & 63;
        float w;
        if      (o < 32) w = Wq[o * 64 + c];
        else if (o < 64) w = Wk[(o - 32) * 64 + c];
        else             w = Wv[(o - 64) * 64 + c];
        wsm[o * 65 + c] = w;
    }
    __syncthreads();

    const int oc = tid;
    float bias;
    if      (oc < 32) bias = bq[oc];
    else if (oc < 64) bias = bk[oc - 32];
    else              bias = bv[oc - 64];

    float acc[32];
#pragma unroll
    for (int p = 0; p < 32; p++) acc[p] = bias;

    const float4* xs4 = (const float4*)xs;
#pragma unroll 8
    for (int c = 0; c < 64; c++) {
        float wv = wsm[oc * 65 + c];
#pragma unroll
        for (int p4 = 0; p4 < 8; p4++) {
            float4 xv = xs4[c * 8 + p4];
            acc[p4 * 4 + 0] += wv * xv.x;
            acc[p4 * 4 + 1] += wv * xv.y;
            acc[p4 * 4 + 2] += wv * xv.z;
            acc[p4 * 4 + 3] += wv * xv.w;
        }
    }

    float s = 0.f, sq = 0.f;
#pragma unroll
    for (int pp = 0; pp < 32; pp++) {
        int q    = imgoff + pp;
        int h    = q >> 7;
        int w2   = q & 127;
        int side = w2 >> 6;
        int w    = w2 & 63;
        int b    = ((h >> 5) << 1) | (w >> 5);
        int l    = ((((h & 31) << 5) | (w & 31)) << 1) | side;
        int nb   = (n << 2) | b;
        float v  = acc[pp];
        if      (oc < 32) g_q[(size_t)(nb * LSEQ + l) * CKD + oc]         = v;
        else if (oc < 64) g_k[(size_t)(nb * LSEQ + l) * CKD + (oc - 32)]  = v;
        else              g_vt[((size_t)nb * CVD + (oc - 64)) * LSEQ + l] = v;
        s += v; sq += v * v;
    }
    if (oc < 64) { atomicAdd(&g_sum[oc], s); atomicAdd(&g_sq[oc], sq); }
}

// ---------------------------------------------------------------- kernel 2: prep (BN fold + split + tile-blob layout)
__global__ __launch_bounds__(256) void prep_kernel(
    const float* __restrict__ gq, const float* __restrict__ betaq,
    const float* __restrict__ gk, const float* __restrict__ betak)
{
    int idx = blockIdx.x * 256 + threadIdx.x;       // 0 .. 2M-1 (pairs)
    if (idx < 1048576) {
        int which = idx >> 19;                      // 0: q, 1: k
        int i = (idx & 524287) * 2;
        int ck = i & 31;
        const float* src = which ? g_k : g_q;
        float2 rv = *(const float2*)(src + i);
        // BN affine on the fly
        const float* gg = which ? gk : gq;
        const float* be = which ? betak : betaq;
        float m0 = g_sum[which * 32 + ck] / NPOSF;
        float v0 = g_sq [which * 32 + ck] / NPOSF - m0 * m0;
        float a0 = gg[ck] * rsqrtf(v0 + EPSB);
        float c0 = be[ck] - m0 * a0;
        float m1 = g_sum[which * 32 + ck + 1] / NPOSF;
        float v1 = g_sq [which * 32 + ck + 1] / NPOSF - m1 * m1;
        float a1 = gg[ck + 1] * rsqrtf(v1 + EPSB);
        float c1 = be[ck + 1] - m1 * a1;
        float y0 = rv.x * a0 + c0;
        float y1 = rv.y * a1 + c1;
        if (!which) { y0 *= SCALE_Q; y1 *= SCALE_Q; }
        uint32_t hw, lw;
        split2(y0, y1, hw, lw);
        if (which) {
            int nb  = i >> 16;
            int rem = i & 65535;
            int l   = rem >> 5;
            int kt  = l >> 7, row = l & 127;
            size_t off = (size_t)(nb * 16 + kt) * TILE_BYTES + row * 80 + ck * 2;
            *(uint32_t*)(g_tiles + off)             = hw;
            *(uint32_t*)(g_tiles + off + BLOB_K_LO) = lw;
        } else {
            int o = i >> 1;
            ((uint32_t*)g_qhi)[o] = hw;
            ((uint32_t*)g_qlo)[o] = lw;
        }
    } else {
        int i = (idx - 1048576) * 2;                // over [nb][cv][l]
        float2 rv = *(const float2*)(g_vt + i);
        uint32_t hw, lw;
        split2(rv.x, rv.y, hw, lw);
        int nb  = i >> 17;
        int rem = i & 131071;
        int cv  = rem >> 11;
        int l   = rem & 2047;
        int kt  = l >> 7, key = l & 127;
        size_t off = (size_t)(nb * 16 + kt) * TILE_BYTES + BLOB_V_HI + cv * 272 + key * 2;
        *(uint32_t*)(g_tiles + off)                         = hw;
        *(uint32_t*)(g_tiles + off + (BLOB_V_LO - BLOB_V_HI)) = lw;
    }
}

// ---------------------------------------------------------------- attention
// smem byte layout:
//  buf b (b=0,1) at b*55296: Khi +0 (pitch 80) | Klo +10240 | Vhi +20480 (pitch 272) | Vlo +37888
//  Q:   110592 (QH +0, QL +10240) pitch 80
//  rs:  131072 (2*128 floats)
//  mbar:132096 (2 x 8B)
#define OFF_Q    110592
#define OFF_RS   131072
#define OFF_MBAR 132096
#define SMEM_BYTES 132352
#define STG_PITCH 66       // float staging overlays offset 0 at the end

extern __shared__ char s_raw[];

__global__ __launch_bounds__(512, 1) void attn_kernel(float* __restrict__ out)
{
    const uint32_t sb = smem_u32(s_raw);
    float* rsarr = (float*)(s_raw + OFF_RS);
    float* stg   = (float*)s_raw;

    const int tid = threadIdx.x;
    const int w   = tid >> 5;
    const int ln  = tid & 31;
    const int qr  = ln >> 2;
    const int qc  = ln & 3;
    const int mb  = w & 7;         // m band: rows mb*16 .. +15
    const int h   = w >> 3;        // key half
    const int nb    = blockIdx.y;
    const int chunk = blockIdx.x;
    const int qbase = chunk * 128;

    const int li   = ln & 7;
    const int tsel = ln >> 3;

    // per-thread ldmatrix base offsets (bytes, within region)
    const uint32_t kbase = (uint32_t)((h * 64 + (tsel >> 1) * 8 + li) * 80 + (tsel & 1) * 16);
    const uint32_t vbase = (uint32_t)(((tsel >> 1) * 8 + li) * 272 + (h * 64 + (tsel & 1) * 8) * 2);
    const uint32_t qfrag = (uint32_t)((mb * 16 + (tsel & 1) * 8 + li) * 80 + (tsel >> 1) * 16);

    const unsigned char* tiles = g_tiles + (size_t)nb * 16 * TILE_BYTES;

    // ---- init mbarriers, kick tile-0 bulk copy, stage Q ----
    if (tid == 0) {
        MBARRIER_INIT(sb + OFF_MBAR,     1);
        MBARRIER_INIT(sb + OFF_MBAR + 8, 1);
    }
    __syncthreads();
    if (tid == 0) {
        MBARRIER_EXPECT_TX(sb + OFF_MBAR, TILE_BYTES);
        CP_BULK(sb, tiles, TILE_BYTES, sb + OFF_MBAR);
    }
    for (int f = tid; f < 1024; f += 512) {
        int half = f >> 9, row = (f & 511) >> 2, j = f & 3;
        const size_t src = ((size_t)(nb * LSEQ + qbase + row)) * CKD + j * 8;
        const __nv_bfloat16* g = half ? g_qlo : g_qhi;
        *(uint4*)(s_raw + OFF_Q + half * 10240 + row * 80 + j * 16) = *(const uint4*)(g + src);
    }
    __syncthreads();

    // ---- hoist Q fragments ----
    uint32_t Qh[2][4], Ql[2][4];
#pragma unroll
    for (int s = 0; s < 2; s++) {
        LDSM_X4(Qh[s][0], Qh[s][1], Qh[s][2], Qh[s][3], sb + OFF_Q + s * 32 + qfrag);
        LDSM_X4(Ql[s][0], Ql[s][1], Ql[s][2], Ql[s][3], sb + OFF_Q + 10240 + s * 32 + qfrag);
    }

    float O[8][4];
#pragma unroll
    for (int v = 0; v < 8; v++)
#pragma unroll
        for (int j = 0; j < 4; j++) O[v][j] = 0.f;
    float rs0 = 0.f, rs1 = 0.f;

    for (int kt = 0; kt < 16; kt++) {
        // wait for this tile's data, then (all warps idle-synced) prefetch next
        MBARRIER_WAIT_PARITY(sb + OFF_MBAR + (kt & 1) * 8, (kt >> 1) & 1);
        __syncthreads();
        if (tid == 0 && kt < 15) {
            const uint32_t mbn = sb + OFF_MBAR + ((kt + 1) & 1) * 8;
            MBARRIER_EXPECT_TX(mbn, TILE_BYTES);
            CP_BULK(sb + ((kt + 1) & 1) * TILE_BYTES,
                    tiles + (size_t)(kt + 1) * TILE_BYTES, TILE_BYTES, mbn);
        }

        const uint32_t kB = sb + (kt & 1) * TILE_BYTES;
        const uint32_t vB = kB + BLOB_V_HI;

        // ---- fused per key-pair (16 keys): S mma -> exp2 -> split -> PV mma ----
#pragma unroll
        for (int t = 0; t < 4; t++) {
            float P0[4] = {0.f, 0.f, 0.f, 0.f};
            float P1[4] = {0.f, 0.f, 0.f, 0.f};
#pragma unroll
            for (int s = 0; s < 2; s++) {
                uint32_t kh[4], kl[4];
                const uint32_t ko = t * 1280 + s * 32 + kbase;
                LDSM_X4(kh[0], kh[1], kh[2], kh[3], kB + ko);
                LDSM_X4(kl[0], kl[1], kl[2], kl[3], kB + BLOB_K_LO + ko);
                mma_bf16(P0, Qh[s], kh[0], kh[1]);
                mma_bf16(P0, Qh[s], kl[0], kl[1]);
                mma_bf16(P0, Ql[s], kh[0], kh[1]);
                mma_bf16(P1, Qh[s], kh[2], kh[3]);
                mma_bf16(P1, Qh[s], kl[2], kl[3]);
                mma_bf16(P1, Ql[s], kh[2], kh[3]);
            }

#pragma unroll
            for (int j = 0; j < 4; j++) { P0[j] = exp2f(P0[j]); P1[j] = exp2f(P1[j]); }
            rs0 += P0[0] + P0[1] + P1[0] + P1[1];
            rs1 += P0[2] + P0[3] + P1[2] + P1[3];

            uint32_t Ah[4], Al[4];
            split2(P0[0], P0[1], Ah[0], Al[0]);
            split2(P0[2], P0[3], Ah[1], Al[1]);
            split2(P1[0], P1[1], Ah[2], Al[2]);
            split2(P1[2], P1[3], Ah[3], Al[3]);

#pragma unroll
            for (int i = 0; i < 4; i++) {
                const int vp = 2 * i;
                uint32_t vh[4], vl[4];
                const uint32_t vo = vp * 2176 + t * 32 + vbase;
                LDSM_X4(vh[0], vh[1], vh[2], vh[3], vB + vo);
                LDSM_X4(vl[0], vl[1], vl[2], vl[3], vB + (BLOB_V_LO - BLOB_V_HI) + vo);
                mma_bf16(O[vp],     Ah, vh[0], vh[1]);
                mma_bf16(O[vp],     Ah, vl[0], vl[1]);
                mma_bf16(O[vp],     Al, vh[0], vh[1]);
                mma_bf16(O[vp + 1], Ah, vh[2], vh[3]);
                mma_bf16(O[vp + 1], Ah, vl[2], vl[3]);
                mma_bf16(O[vp + 1], Al, vh[2], vh[3]);
            }
        }
    }

    // ---- combine halves, normalize, scatter ----
    rs0 += __shfl_xor_sync(0xffffffffu, rs0, 1);
    rs0 += __shfl_xor_sync(0xffffffffu, rs0, 2);
    rs1 += __shfl_xor_sync(0xffffffffu, rs1, 1);
    rs1 += __shfl_xor_sync(0xffffffffu, rs1, 2);
    const int row0 = mb * 16 + qr;
    if (qc == 0) {
        rsarr[h * 128 + row0]     = rs0;
        rsarr[h * 128 + row0 + 8] = rs1;
    }
    __syncthreads();   // all smem-tile reads done; stg overlay safe

    if (h == 0) {
#pragma unroll
        for (int v = 0; v < 8; v++) {
            int cv = v * 8 + qc * 2;
            *(float2*)&stg[(row0)     * STG_PITCH + cv] = make_float2(O[v][0], O[v][1]);
            *(float2*)&stg[(row0 + 8) * STG_PITCH + cv] = make_float2(O[v][2], O[v][3]);
        }
    }
    __syncthreads();
    if (h == 1) {
#pragma unroll
        for (int v = 0; v < 8; v++) {
            int cv = v * 8 + qc * 2;
            float2* p;
            p = (float2*)&stg[(row0)     * STG_PITCH + cv]; p->x += O[v][0]; p->y += O[v][1];
            p = (float2*)&stg[(row0 + 8) * STG_PITCH + cv]; p->x += O[v][2]; p->y += O[v][3];
        }
    }
    __syncthreads();
    if (tid < 128) rsarr[tid] = 1.0f / (rsarr[tid] + rsarr[128 + tid]);
    __syncthreads();

    const int n = nb >> 2, b = nb & 3;
    const int bi = b >> 1, bj = b & 1;
    for (int e = tid; e < 8192; e += 512) {
        int wl   = e & 31;
        int side = (e >> 5) & 1;
        int hlo  = (e >> 6) & 1;
        int cv   = e >> 7;
        int ll   = hlo * 64 + wl * 2 + side;
        int hh   = bi * 32 + chunk * 2 + hlo;
        int w2   = side * 64 + bj * 32 + wl;
        out[(((size_t)(n * 64 + cv)) * 64 + hh) * 128 + w2] =
            stg[ll * STG_PITCH + cv] * rsarr[ll];
    }
}

// ---------------------------------------------------------------- launch
extern "C" void kernel_launch(void* const* d_in, const int* in_sizes, int n_in,
                              void* d_out, int out_size)
{
    (void)in_sizes; (void)n_in; (void)out_size;
    const float* x     = (const float*)d_in[0];
    const float* Wq    = (const float*)d_in[1];
    const float* bq    = (const float*)d_in[2];
    const float* gq    = (const float*)d_in[3];
    const float* betaq = (const float*)d_in[4];
    const float* Wk    = (const float*)d_in[5];
    const float* bk    = (const float*)d_in[6];
    const float* gk    = (const float*)d_in[7];
    const float* betak = (const float*)d_in[8];
    const float* Wv    = (const float*)d_in[9];
    const float* bv    = (const float*)d_in[10];
    float* out = (float*)d_out;

    cudaFuncSetAttribute(attn_kernel, cudaFuncAttributeMaxDynamicSharedMemorySize,
                         SMEM_BYTES);

    zero_stats_kernel<<<1, 64>>>();
    conv_kernel<<<1024, 128>>>(x, Wq, bq, Wk, bk, Wv, bv);
    prep_kernel<<<8192, 256>>>(gq, betaq, gk, betak);
    attn_kernel<<<dim3(16, 16), 512, SMEM_BYTES>>>(out);
}

// round 7
// speedup vs baseline: 3.9577x; 1.3252x over previous
#include <cuda_runtime.h>
#include <cuda_bf16.h>
#include <math.h>
#include <cstdint>

// ---------------------------------------------------------------- constants
#define NBLK  16
#define LSEQ  2048
#define CKD   32
#define CVD   64
#define NPOSF 32768.0f
#define EPSB  1e-5f
#define SCALE_Q 0.25505654350925196f   // (1/sqrt(32)) * log2(e)

// per-(nb,kt) staged tile blob: [Khi 10240 | Klo 10240 | Vfp16 17408]
#define TILE_BYTES 37888
#define BLOB_K_LO  10240
#define BLOB_V     20480

// ---------------------------------------------------------------- scratch
__device__ float g_q [NBLK * LSEQ * CKD];
__device__ float g_k [NBLK * LSEQ * CKD];
__device__ float g_vt[NBLK * CVD * LSEQ];           // [nb][cv][l]
__device__ __nv_bfloat16 g_qhi[NBLK * LSEQ * CKD];
__device__ __nv_bfloat16 g_qlo[NBLK * LSEQ * CKD];
__device__ __align__(128) unsigned char g_tiles[NBLK * 16 * TILE_BYTES];
__device__ float g_sum[64], g_sq[64];   // zero at load; attn re-zeroes each call

// ---------------------------------------------------------------- helpers
__device__ __forceinline__ void mma_bf16(float* c, const uint32_t* a,
                                         uint32_t b0, uint32_t b1) {
    asm volatile(
        "mma.sync.aligned.m16n8k16.row.col.f32.bf16.bf16.f32 "
        "{%0,%1,%2,%3}, {%4,%5,%6,%7}, {%8,%9}, {%0,%1,%2,%3};"
        : "+f"(c[0]), "+f"(c[1]), "+f"(c[2]), "+f"(c[3])
        : "r"(a[0]), "r"(a[1]), "r"(a[2]), "r"(a[3]), "r"(b0), "r"(b1));
}
__device__ __forceinline__ void mma_f16(float* c, const uint32_t* a,
                                        uint32_t b0, uint32_t b1) {
    asm volatile(
        "mma.sync.aligned.m16n8k16.row.col.f32.f16.f16.f32 "
        "{%0,%1,%2,%3}, {%4,%5,%6,%7}, {%8,%9}, {%0,%1,%2,%3};"
        : "+f"(c[0]), "+f"(c[1]), "+f"(c[2]), "+f"(c[3])
        : "r"(a[0]), "r"(a[1]), "r"(a[2]), "r"(a[3]), "r"(b0), "r"(b1));
}
__device__ __forceinline__ uint32_t pack_bf16x2(float lo, float hi) {
    uint32_t r;
    asm("cvt.rn.bf16x2.f32 %0, %1, %2;" : "=r"(r) : "f"(hi), "f"(lo));
    return r;
}
__device__ __forceinline__ uint32_t pack_f16x2(float lo, float hi) {
    uint32_t r;
    asm("cvt.rn.f16x2.f32 %0, %1, %2;" : "=r"(r) : "f"(hi), "f"(lo));
    return r;
}
__device__ __forceinline__ void split2(float p0, float p1, uint32_t& hw, uint32_t& lw) {
    hw = pack_bf16x2(p0, p1);
    float h0 = __uint_as_float(hw << 16);
    float h1 = __uint_as_float(hw & 0xffff0000u);
    lw = pack_bf16x2(p0 - h0, p1 - h1);
}
#define LDSM_X4(r0, r1, r2, r3, addr) \
    asm volatile("ldmatrix.sync.aligned.m8n8.x4.shared.b16 {%0,%1,%2,%3}, [%4];" \
        : "=r"(r0), "=r"(r1), "=r"(r2), "=r"(r3) : "r"(addr))

#define MBARRIER_INIT(mb, cnt) \
    asm volatile("mbarrier.init.shared.b64 [%0], %1;" :: "r"((uint32_t)(mb)), "r"((uint32_t)(cnt)) : "memory")
#define MBARRIER_EXPECT_TX(mb, bytes) \
    asm volatile("mbarrier.arrive.expect_tx.shared.b64 _, [%0], %1;" :: "r"((uint32_t)(mb)), "r"((uint32_t)(bytes)) : "memory")
#define CP_BULK(dst, src, bytes, mbar) \
    asm volatile("cp.async.bulk.shared::cta.global.mbarrier::complete_tx::bytes [%0], [%1], %2, [%3];" \
                 :: "r"((uint32_t)(dst)), "l"(src), "r"((uint32_t)(bytes)), "r"((uint32_t)(mbar)) : "memory")
#define MBARRIER_WAIT_PARITY(mb, par) do {                                          \
    uint32_t _mbar = (uint32_t)(mb); uint32_t _par = (uint32_t)(par); uint32_t _done;\
    asm volatile("{\n\t.reg .pred p;\n\t"                                           \
        "mbarrier.try_wait.parity.acquire.cta.shared::cta.b64 p, [%1], %2;\n\t"     \
        "selp.b32 %0, 1, 0, p;\n\t}" : "=r"(_done) : "r"(_mbar), "r"(_par) : "memory"); \
    if (!_done) {                                                                   \
        asm volatile("{\n\t.reg .pred P1;\n\t"                                      \
            "WAIT_LOOP_%=:\n\t"                                                     \
            "mbarrier.try_wait.parity.acquire.cta.shared::cta.b64 P1, [%0], %1, 0x989680;\n\t" \
            "@P1 bra.uni WAIT_DONE_%=;\n\t"                                         \
            "bra.uni WAIT_LOOP_%=;\n\t"                                             \
            "WAIT_DONE_%=:\n\t}" :: "r"(_mbar), "r"(_par) : "memory");              \
    } } while (0)

__device__ __forceinline__ uint32_t smem_u32(const void* p) {
    uint32_t a;
    asm("{ .reg .u64 t; cvta.to.shared.u64 t, %1; cvt.u32.u64 %0, t; }" : "=r"(a) : "l"(p));
    return a;
}

// ---------------------------------------------------------------- kernel 1: conv1x1
__global__ __launch_bounds__(128) void conv_kernel(
    const float* __restrict__ x,
    const float* __restrict__ Wq, const float* __restrict__ bq,
    const float* __restrict__ Wk, const float* __restrict__ bk,
    const float* __restrict__ Wv, const float* __restrict__ bv)
{
    __shared__ float xs[64 * 32];
    __shared__ float wsm[128 * 65];
    const int tid = threadIdx.x;
    const int p0  = blockIdx.x * 32;
    const int n      = p0 >> 13;
    const int imgoff = p0 & 8191;

    const float* xbase = x + (size_t)n * 64 * 8192 + imgoff;
    for (int f = tid; f < 64 * 32; f += 128) {
        int c = f >> 5, pos = f & 31;
        xs[c * 32 + pos] = xbase[c * 8192 + pos];
    }
    for (int f = tid; f < 128 * 64; f += 128) {
        int o = f >> 6, c = f & 63;
        float w;
        if      (o < 32) w = Wq[o * 64 + c];
        else if (o < 64) w = Wk[(o - 32) * 64 + c];
        else             w = Wv[(o - 64) * 64 + c];
        wsm[o * 65 + c] = w;
    }
    __syncthreads();

    const int oc = tid;
    float bias;
    if      (oc < 32) bias = bq[oc];
    else if (oc < 64) bias = bk[oc - 32];
    else              bias = bv[oc - 64];

    float acc[32];
#pragma unroll
    for (int p = 0; p < 32; p++) acc[p] = bias;

    const float4* xs4 = (const float4*)xs;
#pragma unroll 8
    for (int c = 0; c < 64; c++) {
        float wv = wsm[oc * 65 + c];
#pragma unroll
        for (int p4 = 0; p4 < 8; p4++) {
            float4 xv = xs4[c * 8 + p4];
            acc[p4 * 4 + 0] += wv * xv.x;
            acc[p4 * 4 + 1] += wv * xv.y;
            acc[p4 * 4 + 2] += wv * xv.z;
            acc[p4 * 4 + 3] += wv * xv.w;
        }
    }

    float s = 0.f, sq = 0.f;
#pragma unroll
    for (int pp = 0; pp < 32; pp++) {
        int q    = imgoff + pp;
        int h    = q >> 7;
        int w2   = q & 127;
        int side = w2 >> 6;
        int w    = w2 & 63;
        int b    = ((h >> 5) << 1) | (w >> 5);
        int l    = ((((h & 31) << 5) | (w & 31)) << 1) | side;
        int nb   = (n << 2) | b;
        float v  = acc[pp];
        if      (oc < 32) g_q[(size_t)(nb * LSEQ + l) * CKD + oc]         = v;
        else if (oc < 64) g_k[(size_t)(nb * LSEQ + l) * CKD + (oc - 32)]  = v;
        else              g_vt[((size_t)nb * CVD + (oc - 64)) * LSEQ + l] = v;
        s += v; sq += v * v;
    }
    if (oc < 64) { atomicAdd(&g_sum[oc], s); atomicAdd(&g_sq[oc], sq); }
}

// ---------------------------------------------------------------- kernel 2: prep
__global__ __launch_bounds__(256) void prep_kernel(
    const float* __restrict__ gq, const float* __restrict__ betaq,
    const float* __restrict__ gk, const float* __restrict__ betak)
{
    int idx = blockIdx.x * 256 + threadIdx.x;       // 0 .. 2M-1 (pairs)
    if (idx < 1048576) {
        int which = idx >> 19;                      // 0: q, 1: k
        int i = (idx & 524287) * 2;
        int ck = i & 31;
        const float* src = which ? g_k : g_q;
        float2 rv = *(const float2*)(src + i);
        const float* gg = which ? gk : gq;
        const float* be = which ? betak : betaq;
        float m0 = g_sum[which * 32 + ck] / NPOSF;
        float v0 = g_sq [which * 32 + ck] / NPOSF - m0 * m0;
        float a0 = gg[ck] * rsqrtf(v0 + EPSB);
        float c0 = be[ck] - m0 * a0;
        float m1 = g_sum[which * 32 + ck + 1] / NPOSF;
        float v1 = g_sq [which * 32 + ck + 1] / NPOSF - m1 * m1;
        float a1 = gg[ck + 1] * rsqrtf(v1 + EPSB);
        float c1 = be[ck + 1] - m1 * a1;
        float y0 = rv.x * a0 + c0;
        float y1 = rv.y * a1 + c1;
        if (!which) { y0 *= SCALE_Q; y1 *= SCALE_Q; }
        uint32_t hw, lw;
        split2(y0, y1, hw, lw);
        if (which) {
            int nb  = i >> 16;
            int rem = i & 65535;
            int l   = rem >> 5;
            int kt  = l >> 7, row = l & 127;
            size_t off = (size_t)(nb * 16 + kt) * TILE_BYTES + row * 80 + ck * 2;
            *(uint32_t*)(g_tiles + off)             = hw;
            *(uint32_t*)(g_tiles + off + BLOB_K_LO) = lw;
        } else {
            int o = i >> 1;
            ((uint32_t*)g_qhi)[o] = hw;
            ((uint32_t*)g_qlo)[o] = lw;
        }
    } else {
        int i = (idx - 1048576) * 2;                // over [nb][cv][l]
        float2 rv = *(const float2*)(g_vt + i);
        uint32_t hw = pack_f16x2(rv.x, rv.y);
        int nb  = i >> 17;
        int rem = i & 131071;
        int cv  = rem >> 11;
        int l   = rem & 2047;
        int kt  = l >> 7, key = l & 127;
        size_t off = (size_t)(nb * 16 + kt) * TILE_BYTES + BLOB_V + cv * 272 + key * 2;
        *(uint32_t*)(g_tiles + off) = hw;
    }
}

// ---------------------------------------------------------------- attention
// smem byte layout:
//  buf b (b=0,1) at b*37888: Khi +0 (pitch 80) | Klo +10240 | V +20480 (fp16, pitch 272)
//  Q:   75776 (QH +0, QL +10240) pitch 80
//  rs:  96256 (2*128 floats)
//  mbar:97280 (2 x 8B)
#define OFF_Q    75776
#define OFF_RS   96256
#define OFF_MBAR 97280
#define SMEM_BYTES 97536
#define STG_PITCH 66       // float staging overlays offset 0 at the end

extern __shared__ char s_raw[];

__global__ __launch_bounds__(512, 1) void attn_kernel(float* __restrict__ out)
{
    const uint32_t sb = smem_u32(s_raw);
    float* rsarr = (float*)(s_raw + OFF_RS);
    float* stg   = (float*)s_raw;

    const int tid = threadIdx.x;
    const int w   = tid >> 5;
    const int ln  = tid & 31;
    const int qr  = ln >> 2;
    const int qc  = ln & 3;
    const int mb  = w & 7;         // m band: rows mb*16 .. +15
    const int h   = w >> 3;        // key half
    const int nb    = blockIdx.y;
    const int chunk = blockIdx.x;
    const int qbase = chunk * 128;

    const int li   = ln & 7;
    const int tsel = ln >> 3;

    const uint32_t kbase = (uint32_t)((h * 64 + (tsel >> 1) * 8 + li) * 80 + (tsel & 1) * 16);
    const uint32_t vbase = (uint32_t)(((tsel >> 1) * 8 + li) * 272 + (h * 64 + (tsel & 1) * 8) * 2);
    const uint32_t qfrag = (uint32_t)((mb * 16 + (tsel & 1) * 8 + li) * 80 + (tsel >> 1) * 16);

    const unsigned char* tiles = g_tiles + (size_t)nb * 16 * TILE_BYTES;

    // ---- init mbarriers, kick tile-0 bulk copy, stage Q ----
    if (tid == 0) {
        MBARRIER_INIT(sb + OFF_MBAR,     1);
        MBARRIER_INIT(sb + OFF_MBAR + 8, 1);
    }
    __syncthreads();
    if (tid == 0) {
        MBARRIER_EXPECT_TX(sb + OFF_MBAR, TILE_BYTES);
        CP_BULK(sb, tiles, TILE_BYTES, sb + OFF_MBAR);
    }
    for (int f = tid; f < 1024; f += 512) {
        int half = f >> 9, row = (f & 511) >> 2, j = f & 3;
        const size_t src = ((size_t)(nb * LSEQ + qbase + row)) * CKD + j * 8;
        const __nv_bfloat16* g = half ? g_qlo : g_qhi;
        *(uint4*)(s_raw + OFF_Q + half * 10240 + row * 80 + j * 16) = *(const uint4*)(g + src);
    }
    __syncthreads();

    // ---- hoist Q fragments ----
    uint32_t Qh[2][4], Ql[2][4];
#pragma unroll
    for (int s = 0; s < 2; s++) {
        LDSM_X4(Qh[s][0], Qh[s][1], Qh[s][2], Qh[s][3], sb + OFF_Q + s * 32 + qfrag);
        LDSM_X4(Ql[s][0], Ql[s][1], Ql[s][2], Ql[s][3], sb + OFF_Q + 10240 + s * 32 + qfrag);
    }

    float O[8][4];
#pragma unroll
    for (int v = 0; v < 8; v++)
#pragma unroll
        for (int j = 0; j < 4; j++) O[v][j] = 0.f;
    float rs0 = 0.f, rs1 = 0.f;

    for (int kt = 0; kt < 16; kt++) {
        MBARRIER_WAIT_PARITY(sb + OFF_MBAR + (kt & 1) * 8, (kt >> 1) & 1);
        __syncthreads();
        if (tid == 0 && kt < 15) {
            const uint32_t mbn = sb + OFF_MBAR + ((kt + 1) & 1) * 8;
            MBARRIER_EXPECT_TX(mbn, TILE_BYTES);
            CP_BULK(sb + ((kt + 1) & 1) * TILE_BYTES,
                    tiles + (size_t)(kt + 1) * TILE_BYTES, TILE_BYTES, mbn);
        }

        const uint32_t kB = sb + (kt & 1) * TILE_BYTES;
        const uint32_t vB = kB + BLOB_V;

        // ---- fused per key-pair (16 keys): S mma -> exp2 -> fp16 pack -> PV mma ----
#pragma unroll
        for (int t = 0; t < 4; t++) {
            float P0[4] = {0.f, 0.f, 0.f, 0.f};
            float P1[4] = {0.f, 0.f, 0.f, 0.f};
#pragma unroll
            for (int s = 0; s < 2; s++) {
                uint32_t kh[4], kl[4];
                const uint32_t ko = t * 1280 + s * 32 + kbase;
                LDSM_X4(kh[0], kh[1], kh[2], kh[3], kB + ko);
                LDSM_X4(kl[0], kl[1], kl[2], kl[3], kB + BLOB_K_LO + ko);
                mma_bf16(P0, Qh[s], kh[0], kh[1]);
                mma_bf16(P0, Qh[s], kl[0], kl[1]);
                mma_bf16(P0, Ql[s], kh[0], kh[1]);
                mma_bf16(P1, Qh[s], kh[2], kh[3]);
                mma_bf16(P1, Qh[s], kl[2], kl[3]);
                mma_bf16(P1, Ql[s], kh[2], kh[3]);
            }

#pragma unroll
            for (int j = 0; j < 4; j++) { P0[j] = exp2f(P0[j]); P1[j] = exp2f(P1[j]); }
            rs0 += P0[0] + P0[1] + P1[0] + P1[1];
            rs1 += P0[2] + P0[3] + P1[2] + P1[3];

            uint32_t A[4];
            A[0] = pack_f16x2(P0[0], P0[1]);
            A[1] = pack_f16x2(P0[2], P0[3]);
            A[2] = pack_f16x2(P1[0], P1[1]);
            A[3] = pack_f16x2(P1[2], P1[3]);

#pragma unroll
            for (int i = 0; i < 4; i++) {
                const int vp = 2 * i;
                uint32_t vh[4];
                const uint32_t vo = vp * 2176 + t * 32 + vbase;
                LDSM_X4(vh[0], vh[1], vh[2], vh[3], vB + vo);
                mma_f16(O[vp],     A, vh[0], vh[1]);
                mma_f16(O[vp + 1], A, vh[2], vh[3]);
            }
        }
    }

    // ---- combine halves, normalize, scatter ----
    rs0 += __shfl_xor_sync(0xffffffffu, rs0, 1);
    rs0 += __shfl_xor_sync(0xffffffffu, rs0, 2);
    rs1 += __shfl_xor_sync(0xffffffffu, rs1, 1);
    rs1 += __shfl_xor_sync(0xffffffffu, rs1, 2);
    const int row0 = mb * 16 + qr;
    if (qc == 0) {
        rsarr[h * 128 + row0]     = rs0;
        rsarr[h * 128 + row0 + 8] = rs1;
    }
    __syncthreads();   // all smem-tile reads done; stg overlay safe

    if (h == 0) {
#pragma unroll
        for (int v = 0; v < 8; v++) {
            int cv = v * 8 + qc * 2;
            *(float2*)&stg[(row0)     * STG_PITCH + cv] = make_float2(O[v][0], O[v][1]);
            *(float2*)&stg[(row0 + 8) * STG_PITCH + cv] = make_float2(O[v][2], O[v][3]);
        }
    }
    __syncthreads();
    if (h == 1) {
#pragma unroll
        for (int v = 0; v < 8; v++) {
            int cv = v * 8 + qc * 2;
            float2* p;
            p = (float2*)&stg[(row0)     * STG_PITCH + cv]; p->x += O[v][0]; p->y += O[v][1];
            p = (float2*)&stg[(row0 + 8) * STG_PITCH + cv]; p->x += O[v][2]; p->y += O[v][3];
        }
    }
    __syncthreads();
    if (tid < 128) rsarr[tid] = 1.0f / (rsarr[tid] + rsarr[128 + tid]);
    __syncthreads();

    const int n = nb >> 2, b = nb & 3;
    const int bi = b >> 1, bj = b & 1;
    for (int e = tid; e < 8192; e += 512) {
        int wl   = e & 31;
        int side = (e >> 5) & 1;
        int hlo  = (e >> 6) & 1;
        int cv   = e >> 7;
        int ll   = hlo * 64 + wl * 2 + side;
        int hh   = bi * 32 + chunk * 2 + hlo;
        int w2   = side * 64 + bj * 32 + wl;
        out[(((size_t)(n * 64 + cv)) * 64 + hh) * 128 + w2] =
            stg[ll * STG_PITCH + cv] * rsarr[ll];
    }

    // re-zero BN stat accumulators for the next launch (deterministic state)
    if (blockIdx.x == 0 && blockIdx.y == 0 && tid < 64) {
        g_sum[tid] = 0.f;
        g_sq[tid]  = 0.f;
    }
}

// ---------------------------------------------------------------- launch
extern "C" void kernel_launch(void* const* d_in, const int* in_sizes, int n_in,
                              void* d_out, int out_size)
{
    (void)in_sizes; (void)n_in; (void)out_size;
    const float* x     = (const float*)d_in[0];
    const float* Wq    = (const float*)d_in[1];
    const float* bq    = (const float*)d_in[2];
    const float* gq    = (const float*)d_in[3];
    const float* betaq = (const float*)d_in[4];
    const float* Wk    = (const float*)d_in[5];
    const float* bk    = (const float*)d_in[6];
    const float* gk    = (const float*)d_in[7];
    const float* betak = (const float*)d_in[8];
    const float* Wv    = (const float*)d_in[9];
    const float* bv    = (const float*)d_in[10];
    float* out = (float*)d_out;

    cudaFuncSetAttribute(attn_kernel, cudaFuncAttributeMaxDynamicSharedMemorySize,
                         SMEM_BYTES);

    conv_kernel<<<1024, 128>>>(x, Wq, bq, Wk, bk, Wv, bv);
    prep_kernel<<<8192, 256>>>(gq, betaq, gk, betak);
    attn_kernel<<<dim3(16, 16), 512, SMEM_BYTES>>>(out);
}